// round 1
// baseline (speedup 1.0000x reference)
#include <cuda_runtime.h>

#define NB    8
#define SENC  2048
#define SDEC  1024
#define DIN   512
#define UNITS 512

// Scratch (allocation-free rule: __device__ globals)
__device__ float g_q[(size_t)NB * SDEC * UNITS];            // 16.8 MB
__device__ float g_k[(size_t)NB * SENC * UNITS];            // 33.6 MB
__device__ float g_v[(size_t)NB * SENC * UNITS];            // 33.6 MB
__device__ float g_s[(size_t)NB * SDEC * SENC];             // 67.1 MB

// ---------------------------------------------------------------------------
// Tiled SGEMM: C[M,N] = A[M,K] * B  (B is [K,N] row-major if !BT, [N,K] if BT)
// BM=BN=128, BK=8, 256 threads, 8x8 per-thread microtile.
// All dims assumed multiples of the tile sizes (true for every call here).
// ---------------------------------------------------------------------------
template <bool BT>
__global__ void __launch_bounds__(256, 2)
sgemm128(const float* __restrict__ A, const float* __restrict__ Bm,
         float* __restrict__ C, int M, int N, int K,
         long long sA, long long sB, long long sC)
{
    constexpr int BM = 128, BN = 128, BK = 8;
    A  += (long long)blockIdx.z * sA;
    Bm += (long long)blockIdx.z * sB;
    C  += (long long)blockIdx.z * sC;

    const int m0 = blockIdx.y * BM;
    const int n0 = blockIdx.x * BN;

    __shared__ float As[BK][BM];
    __shared__ float Bs[BK][BN];

    const int tid = threadIdx.x;
    const int tx  = tid & 15;   // n-dir (16)
    const int ty  = tid >> 4;   // m-dir (16)

    float acc[8][8] = {};

    // A tile load mapping: 128 rows x 8 cols -> one float4 per thread
    const int arow = tid >> 1;          // 0..127
    const int agrp = (tid & 1) * 4;     // 0 or 4

    for (int k0 = 0; k0 < K; k0 += BK) {
        // load A tile (transposed into As[k][m])
        float4 av = *(const float4*)(A + (long long)(m0 + arow) * K + k0 + agrp);
        As[agrp + 0][arow] = av.x;
        As[agrp + 1][arow] = av.y;
        As[agrp + 2][arow] = av.z;
        As[agrp + 3][arow] = av.w;

        // load B tile into Bs[k][n]
        if (BT) {
            // B is [N,K] row-major: Bs[k][n] = B[(n0+n)*K + k0+k]
            const int brow = tid >> 1;
            const int bgrp = (tid & 1) * 4;
            float4 bv = *(const float4*)(Bm + (long long)(n0 + brow) * K + k0 + bgrp);
            Bs[bgrp + 0][brow] = bv.x;
            Bs[bgrp + 1][brow] = bv.y;
            Bs[bgrp + 2][brow] = bv.z;
            Bs[bgrp + 3][brow] = bv.w;
        } else {
            // B is [K,N] row-major: direct float4 copy
            const int bk = tid >> 5;          // 0..7
            const int bn = (tid & 31) * 4;    // 0..124
            float4 bv = *(const float4*)(Bm + (long long)(k0 + bk) * N + n0 + bn);
            *(float4*)&Bs[bk][bn] = bv;
        }
        __syncthreads();

        #pragma unroll
        for (int k = 0; k < BK; k++) {
            float a[8], b[8];
            *(float4*)&a[0] = *(const float4*)&As[k][ty * 8];
            *(float4*)&a[4] = *(const float4*)&As[k][ty * 8 + 4];
            *(float4*)&b[0] = *(const float4*)&Bs[k][tx * 8];
            *(float4*)&b[4] = *(const float4*)&Bs[k][tx * 8 + 4];
            #pragma unroll
            for (int i = 0; i < 8; i++)
                #pragma unroll
                for (int j = 0; j < 8; j++)
                    acc[i][j] += a[i] * b[j];
        }
        __syncthreads();
    }

    #pragma unroll
    for (int i = 0; i < 8; i++) {
        float4 c0 = make_float4(acc[i][0], acc[i][1], acc[i][2], acc[i][3]);
        float4 c1 = make_float4(acc[i][4], acc[i][5], acc[i][6], acc[i][7]);
        float* crow = C + (long long)(m0 + ty * 8 + i) * N + n0 + tx * 8;
        *(float4*)(crow)     = c0;
        *(float4*)(crow + 4) = c1;
    }
}

// ---------------------------------------------------------------------------
// Row softmax over 2048 columns; one block (256 threads) per row.
// ---------------------------------------------------------------------------
__inline__ __device__ float warpMax(float v) {
    #pragma unroll
    for (int o = 16; o; o >>= 1) v = fmaxf(v, __shfl_xor_sync(0xffffffffu, v, o));
    return v;
}
__inline__ __device__ float warpSum(float v) {
    #pragma unroll
    for (int o = 16; o; o >>= 1) v += __shfl_xor_sync(0xffffffffu, v, o);
    return v;
}

__global__ void __launch_bounds__(256)
softmax2048(float* __restrict__ S)
{
    const long long row = blockIdx.x;
    float4* p = (float4*)(S + row * (long long)SENC);
    const int tid  = threadIdx.x;
    const int lane = tid & 31;
    const int wid  = tid >> 5;

    float4 v0 = p[tid];
    float4 v1 = p[tid + 256];

    float m = fmaxf(fmaxf(fmaxf(v0.x, v0.y), fmaxf(v0.z, v0.w)),
                    fmaxf(fmaxf(v1.x, v1.y), fmaxf(v1.z, v1.w)));

    __shared__ float smax[8];
    __shared__ float ssum[8];

    m = warpMax(m);
    if (lane == 0) smax[wid] = m;
    __syncthreads();
    float bm = smax[0];
    #pragma unroll
    for (int i = 1; i < 8; i++) bm = fmaxf(bm, smax[i]);

    v0.x = __expf(v0.x - bm); v0.y = __expf(v0.y - bm);
    v0.z = __expf(v0.z - bm); v0.w = __expf(v0.w - bm);
    v1.x = __expf(v1.x - bm); v1.y = __expf(v1.y - bm);
    v1.z = __expf(v1.z - bm); v1.w = __expf(v1.w - bm);

    float s = (v0.x + v0.y + v0.z + v0.w) + (v1.x + v1.y + v1.z + v1.w);
    s = warpSum(s);
    if (lane == 0) ssum[wid] = s;
    __syncthreads();
    float bs = 0.f;
    #pragma unroll
    for (int i = 0; i < 8; i++) bs += ssum[i];

    const float inv = 1.0f / bs;
    v0.x *= inv; v0.y *= inv; v0.z *= inv; v0.w *= inv;
    v1.x *= inv; v1.y *= inv; v1.z *= inv; v1.w *= inv;

    p[tid]       = v0;
    p[tid + 256] = v1;
}

// ---------------------------------------------------------------------------
extern "C" void kernel_launch(void* const* d_in, const int* in_sizes, int n_in,
                              void* d_out, int out_size)
{
    const float* enc = (const float*)d_in[0];  // [8,2048,512]
    const float* dec = (const float*)d_in[1];  // [8,1024,512]
    const float* Wq  = (const float*)d_in[2];  // [512,512]
    const float* Wk  = (const float*)d_in[3];
    const float* Wv  = (const float*)d_in[4];
    float* out = (float*)d_out;                // [8,1024,512]

    float *q, *k, *v, *s;
    cudaGetSymbolAddress((void**)&q, g_q);
    cudaGetSymbolAddress((void**)&k, g_k);
    cudaGetSymbolAddress((void**)&v, g_v);
    cudaGetSymbolAddress((void**)&s, g_s);

    dim3 blk(256);

    // Projections: batch folded into M (row-major contiguous).
    // Q = dec @ Wq : M=8192,  N=512, K=512   (NN)
    sgemm128<false><<<dim3(UNITS / 128, (NB * SDEC) / 128, 1), blk>>>(
        dec, Wq, q, NB * SDEC, UNITS, DIN, 0, 0, 0);
    // K = enc @ Wk : M=16384, N=512, K=512   (NN)
    sgemm128<false><<<dim3(UNITS / 128, (NB * SENC) / 128, 1), blk>>>(
        enc, Wk, k, NB * SENC, UNITS, DIN, 0, 0, 0);
    // V = enc @ Wv
    sgemm128<false><<<dim3(UNITS / 128, (NB * SENC) / 128, 1), blk>>>(
        enc, Wv, v, NB * SENC, UNITS, DIN, 0, 0, 0);

    // S[b] = Q[b] @ K[b]^T : M=1024, N=2048, K=512  (NT), batched over z
    sgemm128<true><<<dim3(SENC / 128, SDEC / 128, NB), blk>>>(
        q, k, s, SDEC, SENC, UNITS,
        (long long)SDEC * UNITS, (long long)SENC * UNITS,
        (long long)SDEC * SENC);

    // softmax over rows of S (8*1024 rows x 2048)
    softmax2048<<<NB * SDEC, 256>>>(s);

    // O[b] = P[b] @ V[b] : M=1024, N=512, K=2048  (NN), batched over z
    sgemm128<false><<<dim3(UNITS / 128, SDEC / 128, NB), blk>>>(
        s, v, out, SDEC, UNITS, SENC,
        (long long)SDEC * SENC, (long long)SENC * UNITS,
        (long long)SDEC * UNITS);
}

// round 2
// speedup vs baseline: 2.0979x; 2.0979x over previous
#include <cuda_runtime.h>
#include <cuda_bf16.h>
#include <cstdint>

#define NB    8
#define SENC  2048
#define SDEC  1024
#define DIN   512
#define UNITS 512

using bf16 = __nv_bfloat16;

// ---------------------------------------------------------------------------
// Scratch (__device__ globals: allocation-free rule)
// ---------------------------------------------------------------------------
__device__ bf16 g_dec_h[(size_t)NB * SDEC * DIN];
__device__ bf16 g_dec_l[(size_t)NB * SDEC * DIN];
__device__ bf16 g_enc_h[(size_t)NB * SENC * DIN];
__device__ bf16 g_enc_l[(size_t)NB * SENC * DIN];
__device__ bf16 g_wqT_h[DIN * UNITS];
__device__ bf16 g_wqT_l[DIN * UNITS];
__device__ bf16 g_wkT_h[DIN * UNITS];
__device__ bf16 g_wkT_l[DIN * UNITS];
__device__ bf16 g_wvT_h[DIN * UNITS];
__device__ bf16 g_wvT_l[DIN * UNITS];
__device__ bf16 g_q_h[(size_t)NB * SDEC * UNITS];
__device__ bf16 g_q_l[(size_t)NB * SDEC * UNITS];
__device__ bf16 g_k_h[(size_t)NB * SENC * UNITS];
__device__ bf16 g_k_l[(size_t)NB * SENC * UNITS];
__device__ bf16 g_vt_h[(size_t)NB * UNITS * SENC];   // V^T per batch: [b][u][s]
__device__ bf16 g_vt_l[(size_t)NB * UNITS * SENC];
__device__ float g_s[(size_t)NB * SDEC * SENC];      // fp32 scores
__device__ bf16 g_p_h[(size_t)NB * SDEC * SENC];     // softmax split
__device__ bf16 g_p_l[(size_t)NB * SDEC * SENC];

// ---------------------------------------------------------------------------
// helpers
// ---------------------------------------------------------------------------
__device__ __forceinline__ void split2(float x, bf16& h, bf16& l) {
    h = __float2bfloat16(x);
    l = __float2bfloat16(x - __bfloat162float(h));
}

#define CPA(dst, src) asm volatile( \
    "cp.async.cg.shared.global [%0], [%1], 16;" :: "r"(dst), "l"(src))
#define CP_COMMIT() asm volatile("cp.async.commit_group;")
#define CP_WAIT0()  asm volatile("cp.async.wait_group 0;")

#define LDSM4(r0,r1,r2,r3,addr) asm volatile( \
    "ldmatrix.sync.aligned.m8n8.x4.shared.b16 {%0,%1,%2,%3}, [%4];" \
    : "=r"(r0),"=r"(r1),"=r"(r2),"=r"(r3) : "r"(addr))

#define LDSM2(r0,r1,addr) asm volatile( \
    "ldmatrix.sync.aligned.m8n8.x2.shared.b16 {%0,%1}, [%2];" \
    : "=r"(r0),"=r"(r1) : "r"(addr))

#define MMA16816(ac,Af,Bf) asm volatile( \
    "mma.sync.aligned.m16n8k16.row.col.f32.bf16.bf16.f32 " \
    "{%0,%1,%2,%3}, {%4,%5,%6,%7}, {%8,%9}, {%0,%1,%2,%3};" \
    : "+f"(ac[0]),"+f"(ac[1]),"+f"(ac[2]),"+f"(ac[3]) \
    : "r"(Af[0]),"r"(Af[1]),"r"(Af[2]),"r"(Af[3]), "r"(Bf[0]),"r"(Bf[1]))

// ---------------------------------------------------------------------------
// NT GEMM with bf16 2-term split operands:
//   C[M,N] = (Ah+Al)[M,K] * (Bh+Bl)[N,K]^T   (dropping Al*Bl)
// Both operands row-major, K contiguous. BM=BN=128, BK=32, 256 threads.
// MODE 0: write fp32 C.  MODE 1: write split bf16 (Chi/Clo) natural layout.
// MODE 2: write split bf16 transposed per 2048-row batch (V^T epilogue).
// ---------------------------------------------------------------------------
constexpr int LDK     = 40;               // padded row pitch (elems), conflict-free
constexpr int TILE_B  = 128 * LDK * 2;    // 10240 bytes / tile
constexpr int STAGE_B = 4 * TILE_B;       // Ah,Al,Bh,Bl
constexpr int SMEM_B  = 2 * STAGE_B;      // double buffered = 81920

__device__ __forceinline__ void stage_load(
    uint32_t sbase, const bf16* Ah, const bf16* Al,
    const bf16* Bh, const bf16* Bl,
    int m0, int n0, int k0, int K, int tid)
{
    const int r  = tid >> 1;           // 0..127
    const int c0 = (tid & 1) * 2;      // chunk base (16B chunks of the 64B row)
    const size_t offA = (size_t)(m0 + r) * K + k0;
    const size_t offB = (size_t)(n0 + r) * K + k0;
    const uint32_t sr = sbase + r * (LDK * 2);
    #pragma unroll
    for (int cc = 0; cc < 2; cc++) {
        const int c = c0 + cc;
        CPA(sr + c * 16,              Ah + offA + c * 8);
        CPA(sr + TILE_B + c * 16,     Al + offA + c * 8);
        CPA(sr + 2 * TILE_B + c * 16, Bh + offB + c * 8);
        CPA(sr + 3 * TILE_B + c * 16, Bl + offB + c * 8);
    }
}

template <int MODE>
__global__ void __launch_bounds__(256, 1)
gemm_nt_split(const bf16* __restrict__ Ah, const bf16* __restrict__ Al,
              const bf16* __restrict__ Bh, const bf16* __restrict__ Bl,
              float* __restrict__ C, bf16* __restrict__ Chi, bf16* __restrict__ Clo,
              int M, int N, int K,
              long long zA, long long zB, long long zC)
{
    extern __shared__ bf16 smem[];
    const int z = blockIdx.z;
    Ah += (long long)z * zA;  Al += (long long)z * zA;
    Bh += (long long)z * zB;  Bl += (long long)z * zB;

    const int m0 = blockIdx.y * 128;
    const int n0 = blockIdx.x * 128;
    const int tid  = threadIdx.x;
    const int wid  = tid >> 5;
    const int lane = tid & 31;
    const int wm = (wid >> 2) * 64;    // warp m offset (2 rows of warps)
    const int wn = (wid & 3) * 32;     // warp n offset (4 cols of warps)

    const uint32_t sm0 = (uint32_t)__cvta_generic_to_shared(smem);

    float acc[4][4][4];
    #pragma unroll
    for (int i = 0; i < 4; i++)
        #pragma unroll
        for (int j = 0; j < 4; j++)
            #pragma unroll
            for (int e = 0; e < 4; e++) acc[i][j][e] = 0.f;

    // ldmatrix lane-address components
    const int a_row = (lane & 7) + ((lane >> 3) & 1) * 8;  // 0..15
    const int a_kad = ((lane >> 4) & 1) * 8;               // 0 or 8
    const int b_row = (lane & 7);
    const int b_kad = ((lane >> 3) & 1) * 8;

    const int nk = K / 32;
    stage_load(sm0, Ah, Al, Bh, Bl, m0, n0, 0, K, tid);
    CP_COMMIT();

    for (int kt = 0; kt < nk; kt++) {
        CP_WAIT0();
        __syncthreads();
        if (kt + 1 < nk) {
            stage_load(sm0 + ((kt + 1) & 1) * STAGE_B,
                       Ah, Al, Bh, Bl, m0, n0, (kt + 1) * 32, K, tid);
            CP_COMMIT();
        }
        const uint32_t sb = sm0 + (kt & 1) * STAGE_B;
        const uint32_t aH = sb, aL = sb + TILE_B;
        const uint32_t bH = sb + 2 * TILE_B, bL = sb + 3 * TILE_B;

        #pragma unroll
        for (int ks = 0; ks < 2; ks++) {
            const int kk = ks * 16;
            uint32_t ah[4][4], al[4][4], bh[4][2], bl[4][2];
            #pragma unroll
            for (int i = 0; i < 4; i++) {
                const uint32_t off =
                    ((wm + i * 16 + a_row) * LDK + kk + a_kad) * 2;
                LDSM4(ah[i][0], ah[i][1], ah[i][2], ah[i][3], aH + off);
                LDSM4(al[i][0], al[i][1], al[i][2], al[i][3], aL + off);
            }
            #pragma unroll
            for (int j = 0; j < 4; j++) {
                const uint32_t off =
                    ((wn + j * 8 + b_row) * LDK + kk + b_kad) * 2;
                LDSM2(bh[j][0], bh[j][1], bH + off);
                LDSM2(bl[j][0], bl[j][1], bL + off);
            }
            #pragma unroll
            for (int i = 0; i < 4; i++)
                #pragma unroll
                for (int j = 0; j < 4; j++) {
                    MMA16816(acc[i][j], ah[i], bh[j]);
                    MMA16816(acc[i][j], ah[i], bl[j]);
                    MMA16816(acc[i][j], al[i], bh[j]);
                }
        }
        __syncthreads();
    }

    // Epilogue
    const int rbase = m0 + wm + (lane >> 2);
    const int cbase = n0 + wn + (lane & 3) * 2;
    #pragma unroll
    for (int i = 0; i < 4; i++) {
        #pragma unroll
        for (int j = 0; j < 4; j++) {
            const int row = rbase + i * 16;
            const int col = cbase + j * 8;
            const float* a = acc[i][j];
            if (MODE == 0) {
                float* c0 = C + (long long)z * zC + (long long)row * N + col;
                float* c1 = C + (long long)z * zC + (long long)(row + 8) * N + col;
                *(float2*)c0 = make_float2(a[0], a[1]);
                *(float2*)c1 = make_float2(a[2], a[3]);
            } else if (MODE == 1) {
                bf16 h0, l0, h1, l1, h2, l2, h3, l3;
                split2(a[0], h0, l0); split2(a[1], h1, l1);
                split2(a[2], h2, l2); split2(a[3], h3, l3);
                size_t i0 = (size_t)row * N + col;
                size_t i1 = (size_t)(row + 8) * N + col;
                *(__nv_bfloat162*)(Chi + i0) = __nv_bfloat162(h0, h1);
                *(__nv_bfloat162*)(Clo + i0) = __nv_bfloat162(l0, l1);
                *(__nv_bfloat162*)(Chi + i1) = __nv_bfloat162(h2, h3);
                *(__nv_bfloat162*)(Clo + i1) = __nv_bfloat162(l2, l3);
            } else {
                // transposed per-batch (rows are b*2048+s, write [b][col][s])
                #pragma unroll
                for (int e = 0; e < 4; e++) {
                    const int rr = row + (e >> 1) * 8;
                    const int nn = col + (e & 1);
                    const size_t idx = (size_t)(rr >> 11) * ((size_t)UNITS * SENC)
                                     + (size_t)nn * SENC + (rr & 2047);
                    bf16 h, l; split2(a[e], h, l);
                    Chi[idx] = h;  Clo[idx] = l;
                }
            }
        }
    }
}

// ---------------------------------------------------------------------------
// fp32 -> bf16 hi/lo split (vectorized)
// ---------------------------------------------------------------------------
__global__ void __launch_bounds__(256)
split4_kernel(const float4* __restrict__ X, __nv_bfloat162* __restrict__ hi,
              __nv_bfloat162* __restrict__ lo, int n4)
{
    int i = blockIdx.x * blockDim.x + threadIdx.x;
    if (i >= n4) return;
    float4 v = X[i];
    bf16 h0,l0,h1,l1,h2,l2,h3,l3;
    split2(v.x,h0,l0); split2(v.y,h1,l1); split2(v.z,h2,l2); split2(v.w,h3,l3);
    hi[2*i]   = __nv_bfloat162(h0,h1);
    hi[2*i+1] = __nv_bfloat162(h2,h3);
    lo[2*i]   = __nv_bfloat162(l0,l1);
    lo[2*i+1] = __nv_bfloat162(l2,l3);
}

// W [K,N] fp32 -> W^T hi/lo [N,K] bf16
__global__ void __launch_bounds__(256)
splitT512_kernel(const float* __restrict__ W, bf16* __restrict__ ht,
                 bf16* __restrict__ lt)
{
    int idx = blockIdx.x * 256 + threadIdx.x;     // 0..262143
    int k = idx >> 9, n = idx & 511;
    bf16 h, l; split2(W[idx], h, l);
    ht[n * 512 + k] = h;
    lt[n * 512 + k] = l;
}

// ---------------------------------------------------------------------------
// Row softmax over 2048 fp32 scores -> split bf16 probabilities
// ---------------------------------------------------------------------------
__inline__ __device__ float warpMax(float v) {
    #pragma unroll
    for (int o = 16; o; o >>= 1) v = fmaxf(v, __shfl_xor_sync(0xffffffffu, v, o));
    return v;
}
__inline__ __device__ float warpSum(float v) {
    #pragma unroll
    for (int o = 16; o; o >>= 1) v += __shfl_xor_sync(0xffffffffu, v, o);
    return v;
}

__global__ void __launch_bounds__(256)
softmax_split(const float* __restrict__ S, bf16* __restrict__ phi,
              bf16* __restrict__ plo)
{
    const long long row = blockIdx.x;
    const float4* p = (const float4*)(S + row * (long long)SENC);
    const int tid = threadIdx.x, lane = tid & 31, wid = tid >> 5;

    float4 v0 = p[tid];
    float4 v1 = p[tid + 256];

    float m = fmaxf(fmaxf(fmaxf(v0.x, v0.y), fmaxf(v0.z, v0.w)),
                    fmaxf(fmaxf(v1.x, v1.y), fmaxf(v1.z, v1.w)));
    __shared__ float smax[8], ssum[8];
    m = warpMax(m);
    if (lane == 0) smax[wid] = m;
    __syncthreads();
    float bm = smax[0];
    #pragma unroll
    for (int i = 1; i < 8; i++) bm = fmaxf(bm, smax[i]);

    v0.x = __expf(v0.x - bm); v0.y = __expf(v0.y - bm);
    v0.z = __expf(v0.z - bm); v0.w = __expf(v0.w - bm);
    v1.x = __expf(v1.x - bm); v1.y = __expf(v1.y - bm);
    v1.z = __expf(v1.z - bm); v1.w = __expf(v1.w - bm);

    float s = (v0.x + v0.y + v0.z + v0.w) + (v1.x + v1.y + v1.z + v1.w);
    s = warpSum(s);
    if (lane == 0) ssum[wid] = s;
    __syncthreads();
    float bs = 0.f;
    #pragma unroll
    for (int i = 0; i < 8; i++) bs += ssum[i];
    const float inv = 1.0f / bs;

    float vv[8] = {v0.x*inv, v0.y*inv, v0.z*inv, v0.w*inv,
                   v1.x*inv, v1.y*inv, v1.z*inv, v1.w*inv};
    bf16 h[8], l[8];
    #pragma unroll
    for (int e = 0; e < 8; e++) split2(vv[e], h[e], l[e]);

    __nv_bfloat162* ph = (__nv_bfloat162*)(phi + row * (long long)SENC);
    __nv_bfloat162* pl = (__nv_bfloat162*)(plo + row * (long long)SENC);
    ph[2*tid]       = __nv_bfloat162(h[0], h[1]);
    ph[2*tid+1]     = __nv_bfloat162(h[2], h[3]);
    ph[512 + 2*tid]   = __nv_bfloat162(h[4], h[5]);
    ph[512 + 2*tid+1] = __nv_bfloat162(h[6], h[7]);
    pl[2*tid]       = __nv_bfloat162(l[0], l[1]);
    pl[2*tid+1]     = __nv_bfloat162(l[2], l[3]);
    pl[512 + 2*tid]   = __nv_bfloat162(l[4], l[5]);
    pl[512 + 2*tid+1] = __nv_bfloat162(l[6], l[7]);
}

// ---------------------------------------------------------------------------
extern "C" void kernel_launch(void* const* d_in, const int* in_sizes, int n_in,
                              void* d_out, int out_size)
{
    const float* enc = (const float*)d_in[0];
    const float* dec = (const float*)d_in[1];
    const float* Wq  = (const float*)d_in[2];
    const float* Wk  = (const float*)d_in[3];
    const float* Wv  = (const float*)d_in[4];
    float* out = (float*)d_out;

    bf16 *dec_h,*dec_l,*enc_h,*enc_l,*wqT_h,*wqT_l,*wkT_h,*wkT_l,*wvT_h,*wvT_l;
    bf16 *q_h,*q_l,*k_h,*k_l,*vt_h,*vt_l,*p_h,*p_l;
    float *s;
    cudaGetSymbolAddress((void**)&dec_h, g_dec_h);
    cudaGetSymbolAddress((void**)&dec_l, g_dec_l);
    cudaGetSymbolAddress((void**)&enc_h, g_enc_h);
    cudaGetSymbolAddress((void**)&enc_l, g_enc_l);
    cudaGetSymbolAddress((void**)&wqT_h, g_wqT_h);
    cudaGetSymbolAddress((void**)&wqT_l, g_wqT_l);
    cudaGetSymbolAddress((void**)&wkT_h, g_wkT_h);
    cudaGetSymbolAddress((void**)&wkT_l, g_wkT_l);
    cudaGetSymbolAddress((void**)&wvT_h, g_wvT_h);
    cudaGetSymbolAddress((void**)&wvT_l, g_wvT_l);
    cudaGetSymbolAddress((void**)&q_h, g_q_h);
    cudaGetSymbolAddress((void**)&q_l, g_q_l);
    cudaGetSymbolAddress((void**)&k_h, g_k_h);
    cudaGetSymbolAddress((void**)&k_l, g_k_l);
    cudaGetSymbolAddress((void**)&vt_h, g_vt_h);
    cudaGetSymbolAddress((void**)&vt_l, g_vt_l);
    cudaGetSymbolAddress((void**)&p_h, g_p_h);
    cudaGetSymbolAddress((void**)&p_l, g_p_l);
    cudaGetSymbolAddress((void**)&s, g_s);

    cudaFuncSetAttribute(gemm_nt_split<0>,
        cudaFuncAttributeMaxDynamicSharedMemorySize, SMEM_B);
    cudaFuncSetAttribute(gemm_nt_split<1>,
        cudaFuncAttributeMaxDynamicSharedMemorySize, SMEM_B);
    cudaFuncSetAttribute(gemm_nt_split<2>,
        cudaFuncAttributeMaxDynamicSharedMemorySize, SMEM_B);

    // 1. input splits
    {
        int n4 = NB * SDEC * DIN / 4;
        split4_kernel<<<(n4 + 255) / 256, 256>>>(
            (const float4*)dec, (__nv_bfloat162*)dec_h, (__nv_bfloat162*)dec_l, n4);
    }
    {
        int n4 = NB * SENC * DIN / 4;
        split4_kernel<<<(n4 + 255) / 256, 256>>>(
            (const float4*)enc, (__nv_bfloat162*)enc_h, (__nv_bfloat162*)enc_l, n4);
    }
    splitT512_kernel<<<1024, 256>>>(Wq, wqT_h, wqT_l);
    splitT512_kernel<<<1024, 256>>>(Wk, wkT_h, wkT_l);
    splitT512_kernel<<<1024, 256>>>(Wv, wvT_h, wvT_l);

    // 2. projections
    gemm_nt_split<1><<<dim3(4, 64, 1), 256, SMEM_B>>>(
        dec_h, dec_l, wqT_h, wqT_l, nullptr, q_h, q_l,
        NB * SDEC, UNITS, DIN, 0, 0, 0);
    gemm_nt_split<1><<<dim3(4, 128, 1), 256, SMEM_B>>>(
        enc_h, enc_l, wkT_h, wkT_l, nullptr, k_h, k_l,
        NB * SENC, UNITS, DIN, 0, 0, 0);
    gemm_nt_split<2><<<dim3(4, 128, 1), 256, SMEM_B>>>(
        enc_h, enc_l, wvT_h, wvT_l, nullptr, vt_h, vt_l,
        NB * SENC, UNITS, DIN, 0, 0, 0);

    // 3. scores S = Q @ K^T (batched)
    gemm_nt_split<0><<<dim3(16, 8, NB), 256, SMEM_B>>>(
        q_h, q_l, k_h, k_l, s, nullptr, nullptr,
        SDEC, SENC, UNITS,
        (long long)SDEC * UNITS, (long long)SENC * UNITS,
        (long long)SDEC * SENC);

    // 4. softmax + split
    softmax_split<<<NB * SDEC, 256>>>(s, p_h, p_l);

    // 5. out = P @ V (batched; B operand = V^T rows)
    gemm_nt_split<0><<<dim3(4, 8, NB), 256, SMEM_B>>>(
        p_h, p_l, vt_h, vt_l, out, nullptr, nullptr,
        SDEC, UNITS, SENC,
        (long long)SDEC * SENC, (long long)UNITS * SENC,
        (long long)SDEC * UNITS);
}

// round 4
// speedup vs baseline: 2.4394x; 1.1628x over previous
#include <cuda_runtime.h>
#include <cuda_bf16.h>
#include <cstdint>

#define NB    8
#define SENC  2048
#define SDEC  1024
#define DIN   512
#define UNITS 512

using bf16 = __nv_bfloat16;

// ---------------------------------------------------------------------------
// Scratch (__device__ globals: allocation-free rule)
// ---------------------------------------------------------------------------
__device__ bf16 g_dec_h[(size_t)NB * SDEC * DIN];
__device__ bf16 g_dec_l[(size_t)NB * SDEC * DIN];
__device__ bf16 g_enc_h[(size_t)NB * SENC * DIN];
__device__ bf16 g_enc_l[(size_t)NB * SENC * DIN];
__device__ bf16 g_wqT_h[DIN * UNITS];
__device__ bf16 g_wqT_l[DIN * UNITS];
__device__ bf16 g_wkT_h[DIN * UNITS];
__device__ bf16 g_wkT_l[DIN * UNITS];
__device__ bf16 g_wvT_h[DIN * UNITS];
__device__ bf16 g_wvT_l[DIN * UNITS];
__device__ bf16 g_q_h[(size_t)NB * SDEC * UNITS];
__device__ bf16 g_q_l[(size_t)NB * SDEC * UNITS];
__device__ bf16 g_k_h[(size_t)NB * SENC * UNITS];
__device__ bf16 g_k_l[(size_t)NB * SENC * UNITS];
__device__ bf16 g_vt_h[(size_t)NB * UNITS * SENC];   // V^T per batch: [b][u][s]
__device__ bf16 g_vt_l[(size_t)NB * UNITS * SENC];
__device__ float g_s[(size_t)NB * SDEC * SENC];      // fp32 scores
__device__ bf16 g_p_h[(size_t)NB * SDEC * SENC];     // softmax split
__device__ bf16 g_p_l[(size_t)NB * SDEC * SENC];

// ---------------------------------------------------------------------------
// helpers
// ---------------------------------------------------------------------------
__device__ __forceinline__ void split2(float x, bf16& h, bf16& l) {
    h = __float2bfloat16(x);
    l = __float2bfloat16(x - __bfloat162float(h));
}

#define CPA(dst, src) asm volatile( \
    "cp.async.cg.shared.global [%0], [%1], 16;" :: "r"(dst), "l"(src))
#define CP_COMMIT() asm volatile("cp.async.commit_group;")
#define CP_WAIT2()  asm volatile("cp.async.wait_group 2;")

#define LDSM4(r0,r1,r2,r3,addr) asm volatile( \
    "ldmatrix.sync.aligned.m8n8.x4.shared.b16 {%0,%1,%2,%3}, [%4];" \
    : "=r"(r0),"=r"(r1),"=r"(r2),"=r"(r3) : "r"(addr))

#define MMA16816(ac,Af,B0,B1) asm volatile( \
    "mma.sync.aligned.m16n8k16.row.col.f32.bf16.bf16.f32 " \
    "{%0,%1,%2,%3}, {%4,%5,%6,%7}, {%8,%9}, {%0,%1,%2,%3};" \
    : "+f"(ac[0]),"+f"(ac[1]),"+f"(ac[2]),"+f"(ac[3]) \
    : "r"(Af[0]),"r"(Af[1]),"r"(Af[2]),"r"(Af[3]), "r"(B0),"r"(B1))

// ---------------------------------------------------------------------------
// NT GEMM, bf16 2-term split (3 MMA terms, Al*Bl dropped):
//   C[M,N] = (Ah+Al)[M,K] * (Bh+Bl)[N,K]^T
// CTA tile 128(M) x 256(N) x 32(K). 8 warps as 2x4, warp tile 64x64.
// 3-stage cp.async pipeline. MODE 0: fp32 C (batched). MODE 1: split bf16.
// MODE 2: split bf16 transposed per 2048-row batch (V^T epilogue).
// ---------------------------------------------------------------------------
constexpr int LDK   = 40;                 // padded pitch (bf16 elems)
constexpr int A_T   = 128 * LDK * 2;      // 10240 B
constexpr int B_T   = 256 * LDK * 2;      // 20480 B
constexpr int STG   = 2 * A_T + 2 * B_T;  // 61440 B per stage
constexpr int NST   = 3;
constexpr int SMEM_B = NST * STG;         // 184320 B

__device__ __forceinline__ void stage_load(
    uint32_t st, const bf16* __restrict__ Ah, const bf16* __restrict__ Al,
    const bf16* __restrict__ Bh, const bf16* __restrict__ Bl,
    int m0, int n0, int k0, int K, int tid)
{
    #pragma unroll
    for (int it = 0; it < 2; it++) {
        const int c = tid + it * 256;          // 512 chunks (A: 128 rows x 4)
        const int row = c >> 2, col = c & 3;
        const uint32_t sa = st + row * (LDK * 2) + col * 16;
        const long long g = (long long)(m0 + row) * K + k0 + col * 8;
        CPA(sa,       Ah + g);
        CPA(sa + A_T, Al + g);
    }
    #pragma unroll
    for (int it = 0; it < 4; it++) {
        const int c = tid + it * 256;          // 1024 chunks (B: 256 rows x 4)
        const int row = c >> 2, col = c & 3;
        const uint32_t sb = st + 2 * A_T + row * (LDK * 2) + col * 16;
        const long long g = (long long)(n0 + row) * K + k0 + col * 8;
        CPA(sb,       Bh + g);
        CPA(sb + B_T, Bl + g);
    }
}

template <int MODE>
__global__ void __launch_bounds__(256, 1)
gemm_nt2(const bf16* __restrict__ Ah, const bf16* __restrict__ Al,
         const bf16* __restrict__ Bh, const bf16* __restrict__ Bl,
         float* __restrict__ C, bf16* __restrict__ OH, bf16* __restrict__ OL,
         int N, int K, long long zA, long long zB, long long zC)
{
    extern __shared__ __align__(128) char smem[];
    const int z = blockIdx.z;
    Ah += (long long)z * zA;  Al += (long long)z * zA;
    Bh += (long long)z * zB;  Bl += (long long)z * zB;

    const int m0 = blockIdx.y * 128;
    const int n0 = blockIdx.x * 256;
    const int tid  = threadIdx.x;
    const int wid  = tid >> 5;
    const int lane = tid & 31;
    const int wm = (wid >> 2) * 64;     // 2 warp-rows
    const int wn = (wid & 3) * 64;      // 4 warp-cols

    const uint32_t sm0 = (uint32_t)__cvta_generic_to_shared(smem);

    float acc[4][8][4];
    #pragma unroll
    for (int i = 0; i < 4; i++)
        #pragma unroll
        for (int j = 0; j < 8; j++)
            #pragma unroll
            for (int e = 0; e < 4; e++) acc[i][j][e] = 0.f;

    // ldmatrix lane addressing
    const int a_row = (lane & 7) + ((lane >> 3) & 1) * 8;
    const int a_kad = ((lane >> 4) & 1) * 8;
    const int b_row = (lane & 7) + ((lane >> 4) & 1) * 8;
    const int b_kad = ((lane >> 3) & 1) * 8;

    const int nk = K / 32;

    // prologue: fill 3 stages
    #pragma unroll
    for (int s = 0; s < NST; s++) {
        stage_load(sm0 + s * STG, Ah, Al, Bh, Bl, m0, n0, s * 32, K, tid);
        CP_COMMIT();
    }

    for (int kt = 0; kt < nk; kt++) {
        CP_WAIT2();
        __syncthreads();
        const uint32_t st = sm0 + (kt % 3) * STG;
        const uint32_t stA = st, stB = st + 2 * A_T;

        #pragma unroll
        for (int ks = 0; ks < 2; ks++) {
            const int kk = ks * 16;
            uint32_t ah[4][4], al[4][4];
            #pragma unroll
            for (int i = 0; i < 4; i++) {
                const uint32_t off =
                    ((wm + i * 16 + a_row) * LDK + kk + a_kad) * 2;
                LDSM4(ah[i][0], ah[i][1], ah[i][2], ah[i][3], stA + off);
                LDSM4(al[i][0], al[i][1], al[i][2], al[i][3], stA + A_T + off);
            }
            #pragma unroll
            for (int j2 = 0; j2 < 4; j2++) {
                uint32_t bh[4], bl[4];
                const uint32_t off =
                    ((wn + j2 * 16 + b_row) * LDK + kk + b_kad) * 2;
                LDSM4(bh[0], bh[1], bh[2], bh[3], stB + off);
                LDSM4(bl[0], bl[1], bl[2], bl[3], stB + B_T + off);
                #pragma unroll
                for (int i = 0; i < 4; i++) {
                    MMA16816(acc[i][2*j2],   ah[i], bh[0], bh[1]);
                    MMA16816(acc[i][2*j2],   ah[i], bl[0], bl[1]);
                    MMA16816(acc[i][2*j2],   al[i], bh[0], bh[1]);
                    MMA16816(acc[i][2*j2+1], ah[i], bh[2], bh[3]);
                    MMA16816(acc[i][2*j2+1], ah[i], bl[2], bl[3]);
                    MMA16816(acc[i][2*j2+1], al[i], bh[2], bh[3]);
                }
            }
        }
        __syncthreads();
        if (kt + NST < nk)
            stage_load(sm0 + (kt % 3) * STG, Ah, Al, Bh, Bl,
                       m0, n0, (kt + NST) * 32, K, tid);
        CP_COMMIT();   // empty group when no load: keeps wait accounting fixed
    }

    // ---- epilogue ----
    const int rr0 = m0 + wm + (lane >> 2);
    const int cc0 = n0 + wn + (lane & 3) * 2;
    #pragma unroll
    for (int i = 0; i < 4; i++) {
        #pragma unroll
        for (int j = 0; j < 8; j++) {
            const float* a = acc[i][j];
            const int r0 = rr0 + i * 16;
            const int c  = cc0 + j * 8;
            if (MODE == 0) {
                float* p0 = C + (long long)z * zC + (long long)r0 * N + c;
                float* p1 = C + (long long)z * zC + (long long)(r0 + 8) * N + c;
                *(float2*)p0 = make_float2(a[0], a[1]);
                *(float2*)p1 = make_float2(a[2], a[3]);
            } else if (MODE == 1) {
                bf16 h0,l0,h1,l1,h2,l2,h3,l3;
                split2(a[0],h0,l0); split2(a[1],h1,l1);
                split2(a[2],h2,l2); split2(a[3],h3,l3);
                const size_t i0 = (size_t)r0 * N + c;
                const size_t i1 = (size_t)(r0 + 8) * N + c;
                *(__nv_bfloat162*)(OH + i0) = __nv_bfloat162(h0, h1);
                *(__nv_bfloat162*)(OL + i0) = __nv_bfloat162(l0, l1);
                *(__nv_bfloat162*)(OH + i1) = __nv_bfloat162(h2, h3);
                *(__nv_bfloat162*)(OL + i1) = __nv_bfloat162(l2, l3);
            } else {
                #pragma unroll
                for (int e = 0; e < 4; e++) {
                    const int rr = r0 + (e >> 1) * 8;
                    const int cn = c + (e & 1);
                    const size_t idx = (size_t)(rr >> 11) * ((size_t)UNITS * SENC)
                                     + (size_t)cn * SENC + (rr & 2047);
                    bf16 h, l; split2(a[e], h, l);
                    OH[idx] = h;  OL[idx] = l;
                }
            }
        }
    }
}

// ---------------------------------------------------------------------------
// fp32 -> bf16 hi/lo split (vectorized)
// ---------------------------------------------------------------------------
__global__ void __launch_bounds__(256)
split4_kernel(const float4* __restrict__ X, __nv_bfloat162* __restrict__ hi,
              __nv_bfloat162* __restrict__ lo, int n4)
{
    int i = blockIdx.x * blockDim.x + threadIdx.x;
    if (i >= n4) return;
    float4 v = X[i];
    bf16 h0,l0,h1,l1,h2,l2,h3,l3;
    split2(v.x,h0,l0); split2(v.y,h1,l1); split2(v.z,h2,l2); split2(v.w,h3,l3);
    hi[2*i]   = __nv_bfloat162(h0,h1);
    hi[2*i+1] = __nv_bfloat162(h2,h3);
    lo[2*i]   = __nv_bfloat162(l0,l1);
    lo[2*i+1] = __nv_bfloat162(l2,l3);
}

// W [K,N] fp32 -> W^T hi/lo [N,K] bf16
__global__ void __launch_bounds__(256)
splitT512_kernel(const float* __restrict__ W, bf16* __restrict__ ht,
                 bf16* __restrict__ lt)
{
    int idx = blockIdx.x * 256 + threadIdx.x;
    int k = idx >> 9, n = idx & 511;
    bf16 h, l; split2(W[idx], h, l);
    ht[n * 512 + k] = h;
    lt[n * 512 + k] = l;
}

// ---------------------------------------------------------------------------
// Row softmax over 2048 fp32 scores -> split bf16 probabilities
// ---------------------------------------------------------------------------
__inline__ __device__ float warpMax(float v) {
    #pragma unroll
    for (int o = 16; o; o >>= 1) v = fmaxf(v, __shfl_xor_sync(0xffffffffu, v, o));
    return v;
}
__inline__ __device__ float warpSum(float v) {
    #pragma unroll
    for (int o = 16; o; o >>= 1) v += __shfl_xor_sync(0xffffffffu, v, o);
    return v;
}

__global__ void __launch_bounds__(256)
softmax_split(const float* __restrict__ S, bf16* __restrict__ phi,
              bf16* __restrict__ plo)
{
    const long long row = blockIdx.x;
    const float4* p = (const float4*)(S + row * (long long)SENC);
    const int tid = threadIdx.x, lane = tid & 31, wid = tid >> 5;

    float4 v0 = p[tid];
    float4 v1 = p[tid + 256];

    float m = fmaxf(fmaxf(fmaxf(v0.x, v0.y), fmaxf(v0.z, v0.w)),
                    fmaxf(fmaxf(v1.x, v1.y), fmaxf(v1.z, v1.w)));
    __shared__ float smax[8], ssum[8];
    m = warpMax(m);
    if (lane == 0) smax[wid] = m;
    __syncthreads();
    float bm = smax[0];
    #pragma unroll
    for (int i = 1; i < 8; i++) bm = fmaxf(bm, smax[i]);

    v0.x = __expf(v0.x - bm); v0.y = __expf(v0.y - bm);
    v0.z = __expf(v0.z - bm); v0.w = __expf(v0.w - bm);
    v1.x = __expf(v1.x - bm); v1.y = __expf(v1.y - bm);
    v1.z = __expf(v1.z - bm); v1.w = __expf(v1.w - bm);

    float s = (v0.x + v0.y + v0.z + v0.w) + (v1.x + v1.y + v1.z + v1.w);
    s = warpSum(s);
    if (lane == 0) ssum[wid] = s;
    __syncthreads();
    float bs = 0.f;
    #pragma unroll
    for (int i = 0; i < 8; i++) bs += ssum[i];
    const float inv = 1.0f / bs;

    float vv[8] = {v0.x*inv, v0.y*inv, v0.z*inv, v0.w*inv,
                   v1.x*inv, v1.y*inv, v1.z*inv, v1.w*inv};
    bf16 h[8], l[8];
    #pragma unroll
    for (int e = 0; e < 8; e++) split2(vv[e], h[e], l[e]);

    __nv_bfloat162* ph = (__nv_bfloat162*)(phi + row * (long long)SENC);
    __nv_bfloat162* pl = (__nv_bfloat162*)(plo + row * (long long)SENC);
    ph[2*tid]         = __nv_bfloat162(h[0], h[1]);
    ph[2*tid+1]       = __nv_bfloat162(h[2], h[3]);
    ph[512 + 2*tid]   = __nv_bfloat162(h[4], h[5]);
    ph[512 + 2*tid+1] = __nv_bfloat162(h[6], h[7]);
    pl[2*tid]         = __nv_bfloat162(l[0], l[1]);
    pl[2*tid+1]       = __nv_bfloat162(l[2], l[3]);
    pl[512 + 2*tid]   = __nv_bfloat162(l[4], l[5]);
    pl[512 + 2*tid+1] = __nv_bfloat162(l[6], l[7]);
}

// ---------------------------------------------------------------------------
extern "C" void kernel_launch(void* const* d_in, const int* in_sizes, int n_in,
                              void* d_out, int out_size)
{
    const float* enc = (const float*)d_in[0];
    const float* dec = (const float*)d_in[1];
    const float* Wq  = (const float*)d_in[2];
    const float* Wk  = (const float*)d_in[3];
    const float* Wv  = (const float*)d_in[4];
    float* out = (float*)d_out;

    bf16 *dec_h,*dec_l,*enc_h,*enc_l,*wqT_h,*wqT_l,*wkT_h,*wkT_l,*wvT_h,*wvT_l;
    bf16 *q_h,*q_l,*k_h,*k_l,*vt_h,*vt_l,*p_h,*p_l;
    float *s;
    cudaGetSymbolAddress((void**)&dec_h, g_dec_h);
    cudaGetSymbolAddress((void**)&dec_l, g_dec_l);
    cudaGetSymbolAddress((void**)&enc_h, g_enc_h);
    cudaGetSymbolAddress((void**)&enc_l, g_enc_l);
    cudaGetSymbolAddress((void**)&wqT_h, g_wqT_h);
    cudaGetSymbolAddress((void**)&wqT_l, g_wqT_l);
    cudaGetSymbolAddress((void**)&wkT_h, g_wkT_h);
    cudaGetSymbolAddress((void**)&wkT_l, g_wkT_l);
    cudaGetSymbolAddress((void**)&wvT_h, g_wvT_h);
    cudaGetSymbolAddress((void**)&wvT_l, g_wvT_l);
    cudaGetSymbolAddress((void**)&q_h, g_q_h);
    cudaGetSymbolAddress((void**)&q_l, g_q_l);
    cudaGetSymbolAddress((void**)&k_h, g_k_h);
    cudaGetSymbolAddress((void**)&k_l, g_k_l);
    cudaGetSymbolAddress((void**)&vt_h, g_vt_h);
    cudaGetSymbolAddress((void**)&vt_l, g_vt_l);
    cudaGetSymbolAddress((void**)&p_h, g_p_h);
    cudaGetSymbolAddress((void**)&p_l, g_p_l);
    cudaGetSymbolAddress((void**)&s, g_s);

    cudaFuncSetAttribute(gemm_nt2<0>, cudaFuncAttributeMaxDynamicSharedMemorySize, SMEM_B);
    cudaFuncSetAttribute(gemm_nt2<1>, cudaFuncAttributeMaxDynamicSharedMemorySize, SMEM_B);
    cudaFuncSetAttribute(gemm_nt2<2>, cudaFuncAttributeMaxDynamicSharedMemorySize, SMEM_B);

    // 1. input splits
    {
        int n4 = NB * SDEC * DIN / 4;
        split4_kernel<<<(n4 + 255) / 256, 256>>>(
            (const float4*)dec, (__nv_bfloat162*)dec_h, (__nv_bfloat162*)dec_l, n4);
    }
    {
        int n4 = NB * SENC * DIN / 4;
        split4_kernel<<<(n4 + 255) / 256, 256>>>(
            (const float4*)enc, (__nv_bfloat162*)enc_h, (__nv_bfloat162*)enc_l, n4);
    }
    splitT512_kernel<<<1024, 256>>>(Wq, wqT_h, wqT_l);
    splitT512_kernel<<<1024, 256>>>(Wk, wkT_h, wkT_l);
    splitT512_kernel<<<1024, 256>>>(Wv, wvT_h, wvT_l);

    // 2. projections (N=512 -> 2 x-tiles)
    gemm_nt2<1><<<dim3(2, (NB*SDEC)/128, 1), 256, SMEM_B>>>(
        dec_h, dec_l, wqT_h, wqT_l, nullptr, q_h, q_l,
        UNITS, DIN, 0, 0, 0);
    gemm_nt2<1><<<dim3(2, (NB*SENC)/128, 1), 256, SMEM_B>>>(
        enc_h, enc_l, wkT_h, wkT_l, nullptr, k_h, k_l,
        UNITS, DIN, 0, 0, 0);
    gemm_nt2<2><<<dim3(2, (NB*SENC)/128, 1), 256, SMEM_B>>>(
        enc_h, enc_l, wvT_h, wvT_l, nullptr, vt_h, vt_l,
        UNITS, DIN, 0, 0, 0);

    // 3. scores S = Q @ K^T (batched over z)
    gemm_nt2<0><<<dim3(SENC/256, SDEC/128, NB), 256, SMEM_B>>>(
        q_h, q_l, k_h, k_l, s, nullptr, nullptr,
        SENC, UNITS,
        (long long)SDEC * UNITS, (long long)SENC * UNITS,
        (long long)SDEC * SENC);

    // 4. softmax + split
    softmax_split<<<NB * SDEC, 256>>>(s, p_h, p_l);

    // 5. out = P @ V (batched; B operand = V^T rows)
    gemm_nt2<0><<<dim3(UNITS/256, SDEC/128, NB), 256, SMEM_B>>>(
        p_h, p_l, vt_h, vt_l, out, nullptr, nullptr,
        UNITS, SENC,
        (long long)SDEC * SENC, (long long)UNITS * SENC,
        (long long)SDEC * UNITS);
}

// round 5
// speedup vs baseline: 2.7375x; 1.1222x over previous
#include <cuda_runtime.h>
#include <cuda_bf16.h>
#include <cuda_fp16.h>
#include <cstdint>

#define NB    8
#define SENC  2048
#define SDEC  1024
#define DIN   512
#define UNITS 512

using bf16 = __nv_bfloat16;

// ---------------------------------------------------------------------------
// Scratch (__device__ globals: allocation-free rule)
// ---------------------------------------------------------------------------
__device__ __align__(256) bf16 g_dec_h[(size_t)NB * SDEC * DIN];
__device__ __align__(256) bf16 g_dec_l[(size_t)NB * SDEC * DIN];
__device__ __align__(256) bf16 g_enc_h[(size_t)NB * SENC * DIN];
__device__ __align__(256) bf16 g_enc_l[(size_t)NB * SENC * DIN];
__device__ __align__(256) bf16 g_wqT_h[DIN * UNITS];
__device__ __align__(256) bf16 g_wqT_l[DIN * UNITS];
__device__ __align__(256) bf16 g_wkT_h[DIN * UNITS];
__device__ __align__(256) bf16 g_wkT_l[DIN * UNITS];
__device__ __align__(256) bf16 g_wvT_h[DIN * UNITS];
__device__ __align__(256) bf16 g_wvT_l[DIN * UNITS];
__device__ __align__(256) bf16 g_q_h[(size_t)NB * SDEC * UNITS];
__device__ __align__(256) bf16 g_q_l[(size_t)NB * SDEC * UNITS];
__device__ __align__(256) bf16 g_k_h[(size_t)NB * SENC * UNITS];
__device__ __align__(256) bf16 g_k_l[(size_t)NB * SENC * UNITS];
__device__ __align__(256) __half g_vt16[(size_t)NB * UNITS * SENC]; // V^T fp16
__device__ __align__(256) float g_s[(size_t)NB * SDEC * SENC];      // fp32 scores
__device__ __align__(256) __half g_p16[(size_t)NB * SDEC * SENC];   // P fp16

// ---------------------------------------------------------------------------
// helpers
// ---------------------------------------------------------------------------
__device__ __forceinline__ void split2(float x, bf16& h, bf16& l) {
    h = __float2bfloat16(x);
    l = __float2bfloat16(x - __bfloat162float(h));
}

#define CPA(dst, src) asm volatile( \
    "cp.async.cg.shared.global [%0], [%1], 16;" :: "r"(dst), "l"(src))
#define CP_COMMIT() asm volatile("cp.async.commit_group;")
#define CP_WAIT2()  asm volatile("cp.async.wait_group 2;")

#define LDSM4(r0,r1,r2,r3,addr) asm volatile( \
    "ldmatrix.sync.aligned.m8n8.x4.shared.b16 {%0,%1,%2,%3}, [%4];" \
    : "=r"(r0),"=r"(r1),"=r"(r2),"=r"(r3) : "r"(addr))

#define MMA_BF16(ac,Af,B0,B1) asm volatile( \
    "mma.sync.aligned.m16n8k16.row.col.f32.bf16.bf16.f32 " \
    "{%0,%1,%2,%3}, {%4,%5,%6,%7}, {%8,%9}, {%0,%1,%2,%3};" \
    : "+f"(ac[0]),"+f"(ac[1]),"+f"(ac[2]),"+f"(ac[3]) \
    : "r"(Af[0]),"r"(Af[1]),"r"(Af[2]),"r"(Af[3]), "r"(B0),"r"(B1))

#define MMA_FP16(ac,Af,B0,B1) asm volatile( \
    "mma.sync.aligned.m16n8k16.row.col.f32.f16.f16.f32 " \
    "{%0,%1,%2,%3}, {%4,%5,%6,%7}, {%8,%9}, {%0,%1,%2,%3};" \
    : "+f"(ac[0]),"+f"(ac[1]),"+f"(ac[2]),"+f"(ac[3]) \
    : "r"(Af[0]),"r"(Af[1]),"r"(Af[2]),"r"(Af[3]), "r"(B0),"r"(B1))

// ---------------------------------------------------------------------------
// Generic NT GEMM mainloop (256 threads, 8 warps as 2x4, BN=256, BK=32).
// IM = number of m16 fragments per warp (BM = 32*IM; warp tile = 16*IM x 64).
// TERMS=3: bf16 2-term split (Ah*Bh + Ah*Bl + Al*Bh). TERMS=1: plain fp16.
// aBase/bBase are element offsets of tile row 0. acc[IM][8][4] in fp32.
// ---------------------------------------------------------------------------
constexpr int NST = 3;

template <int IM, int TERMS, bool FP16>
__device__ __forceinline__ void gemm_mainloop(
    const uint16_t* __restrict__ Ah, const uint16_t* __restrict__ Al,
    const uint16_t* __restrict__ Bh, const uint16_t* __restrict__ Bl,
    long long aBase, long long bBase, int K,
    float acc[][8][4], char* smem)
{
    constexpr int BM   = 32 * IM;
    constexpr int A_TB = BM * 80;       // bytes per A tile (LDK=40 pitch)
    constexpr int B_TB = 256 * 80;
    constexpr int BOFF = (TERMS == 3) ? 2 * A_TB : A_TB;
    constexpr int STG  = (TERMS == 3) ? 2 * (A_TB + B_TB) : (A_TB + B_TB);

    const int tid  = threadIdx.x;
    const int wid  = tid >> 5;
    const int lane = tid & 31;
    const int wm = (wid >> 2) * (BM / 2);
    const int wn = (wid & 3) * 64;

    const uint32_t sm0 = (uint32_t)__cvta_generic_to_shared(smem);

    const int a_row = (lane & 7) + ((lane >> 3) & 1) * 8;
    const int a_kad = ((lane >> 4) & 1) * 8;
    const int b_row = (lane & 7) + ((lane >> 4) & 1) * 8;
    const int b_kad = ((lane >> 3) & 1) * 8;

    const int nk = K / 32;

    auto load_stage = [&](int s, int k0) {
        const uint32_t st = sm0 + s * STG;
        #pragma unroll
        for (int c = tid; c < BM * 4; c += 256) {
            const int row = c >> 2, col = c & 3;
            const uint32_t sa = st + row * 80 + col * 16;
            const long long g = aBase + (long long)row * K + k0 + col * 8;
            CPA(sa, Ah + g);
            if (TERMS == 3) CPA(sa + A_TB, Al + g);
        }
        #pragma unroll
        for (int c = tid; c < 1024; c += 256) {
            const int row = c >> 2, col = c & 3;
            const uint32_t sb = st + BOFF + row * 80 + col * 16;
            const long long g = bBase + (long long)row * K + k0 + col * 8;
            CPA(sb, Bh + g);
            if (TERMS == 3) CPA(sb + B_TB, Bl + g);
        }
    };

    #pragma unroll
    for (int s = 0; s < NST; s++) {
        load_stage(s, s * 32);
        CP_COMMIT();
    }

    for (int kt = 0; kt < nk; kt++) {
        CP_WAIT2();
        __syncthreads();
        const uint32_t st  = sm0 + (kt % 3) * STG;
        const uint32_t stA = st, stB = st + BOFF;

        #pragma unroll
        for (int ks = 0; ks < 2; ks++) {
            const int kk = ks * 16;
            uint32_t ah[IM][4], al[IM][4];
            #pragma unroll
            for (int i = 0; i < IM; i++) {
                const uint32_t off = ((wm + i * 16 + a_row) * 40 + kk + a_kad) * 2;
                LDSM4(ah[i][0], ah[i][1], ah[i][2], ah[i][3], stA + off);
                if (TERMS == 3)
                    LDSM4(al[i][0], al[i][1], al[i][2], al[i][3], stA + A_TB + off);
            }
            #pragma unroll
            for (int j2 = 0; j2 < 4; j2++) {
                uint32_t bh[4], bl[4];
                const uint32_t off = ((wn + j2 * 16 + b_row) * 40 + kk + b_kad) * 2;
                LDSM4(bh[0], bh[1], bh[2], bh[3], stB + off);
                if (TERMS == 3)
                    LDSM4(bl[0], bl[1], bl[2], bl[3], stB + B_TB + off);
                #pragma unroll
                for (int i = 0; i < IM; i++) {
                    if (FP16) {
                        MMA_FP16(acc[i][2*j2],   ah[i], bh[0], bh[1]);
                        MMA_FP16(acc[i][2*j2+1], ah[i], bh[2], bh[3]);
                    } else {
                        MMA_BF16(acc[i][2*j2],   ah[i], bh[0], bh[1]);
                        MMA_BF16(acc[i][2*j2+1], ah[i], bh[2], bh[3]);
                        if (TERMS == 3) {
                            MMA_BF16(acc[i][2*j2],   ah[i], bl[0], bl[1]);
                            MMA_BF16(acc[i][2*j2],   al[i], bh[0], bh[1]);
                            MMA_BF16(acc[i][2*j2+1], ah[i], bl[2], bl[3]);
                            MMA_BF16(acc[i][2*j2+1], al[i], bh[2], bh[3]);
                        }
                    }
                }
            }
        }
        __syncthreads();
        if (kt + NST < nk)
            load_stage(kt % 3, (kt + NST) * 32);
        CP_COMMIT();
    }
}

// ---------------------------------------------------------------------------
// Merged projection kernel: BM=64, BN=256, K=512, TERMS=3 bf16.
// grid = (2, 640): y<128 -> Q (dec*Wq), y<384 -> K (enc*Wk), else V (enc*Wv).
// Q,K epilogue: split bf16. V epilogue: fp16 V^T ([b][u][s]).
// ---------------------------------------------------------------------------
constexpr int SMEM_P3 = NST * 2 * (64 * 80 + 256 * 80);   // 153600

__global__ void __launch_bounds__(256, 1)
proj_kernel(const bf16* dec_h, const bf16* dec_l,
            const bf16* enc_h, const bf16* enc_l,
            const bf16* wq_h, const bf16* wq_l,
            const bf16* wk_h, const bf16* wk_l,
            const bf16* wv_h, const bf16* wv_l,
            bf16* q_h, bf16* q_l, bf16* k_h, bf16* k_l, __half* vt)
{
    extern __shared__ __align__(128) char smem[];
    const int y = blockIdx.y;
    const int n0 = blockIdx.x * 256;

    const uint16_t *Ah, *Al, *Bh, *Bl;
    bf16 *oh = nullptr, *ol = nullptr;
    int mode, arow0;
    if (y < 128) {
        Ah = (const uint16_t*)dec_h; Al = (const uint16_t*)dec_l;
        Bh = (const uint16_t*)wq_h;  Bl = (const uint16_t*)wq_l;
        oh = q_h; ol = q_l; mode = 1; arow0 = y * 64;
    } else if (y < 384) {
        Ah = (const uint16_t*)enc_h; Al = (const uint16_t*)enc_l;
        Bh = (const uint16_t*)wk_h;  Bl = (const uint16_t*)wk_l;
        oh = k_h; ol = k_l; mode = 1; arow0 = (y - 128) * 64;
    } else {
        Ah = (const uint16_t*)enc_h; Al = (const uint16_t*)enc_l;
        Bh = (const uint16_t*)wv_h;  Bl = (const uint16_t*)wv_l;
        mode = 2; arow0 = (y - 384) * 64;
    }

    float acc[2][8][4];
    #pragma unroll
    for (int i = 0; i < 2; i++)
        #pragma unroll
        for (int j = 0; j < 8; j++)
            #pragma unroll
            for (int e = 0; e < 4; e++) acc[i][j][e] = 0.f;

    gemm_mainloop<2, 3, false>(Ah, Al, Bh, Bl,
        (long long)arow0 * DIN, (long long)n0 * DIN, DIN, acc, smem);

    const int wid = threadIdx.x >> 5, lane = threadIdx.x & 31;
    const int rr0 = arow0 + (wid >> 2) * 32 + (lane >> 2);
    const int cc0 = n0 + (wid & 3) * 64 + (lane & 3) * 2;

    #pragma unroll
    for (int i = 0; i < 2; i++) {
        #pragma unroll
        for (int j = 0; j < 8; j++) {
            const float* a = acc[i][j];
            const int r0 = rr0 + i * 16;
            const int c  = cc0 + j * 8;
            if (mode == 1) {
                bf16 h0,l0,h1,l1,h2,l2,h3,l3;
                split2(a[0],h0,l0); split2(a[1],h1,l1);
                split2(a[2],h2,l2); split2(a[3],h3,l3);
                const size_t i0 = (size_t)r0 * UNITS + c;
                const size_t i1 = (size_t)(r0 + 8) * UNITS + c;
                *(__nv_bfloat162*)(oh + i0) = __nv_bfloat162(h0, h1);
                *(__nv_bfloat162*)(ol + i0) = __nv_bfloat162(l0, l1);
                *(__nv_bfloat162*)(oh + i1) = __nv_bfloat162(h2, h3);
                *(__nv_bfloat162*)(ol + i1) = __nv_bfloat162(l2, l3);
            } else {
                #pragma unroll
                for (int e = 0; e < 4; e++) {
                    const int rr = r0 + (e >> 1) * 8;        // enc row
                    const int cn = c + (e & 1);              // unit
                    const size_t idx = (size_t)(rr >> 11) * ((size_t)UNITS * SENC)
                                     + (size_t)cn * SENC + (rr & 2047);
                    vt[idx] = __float2half(a[e]);
                }
            }
        }
    }
}

// ---------------------------------------------------------------------------
// Scores: S[b] = Q[b] @ K[b]^T, BM=64, BN=256, K=512, TERMS=3 bf16, fp32 out.
// grid = (8, 16, 8)
// ---------------------------------------------------------------------------
__global__ void __launch_bounds__(256, 1)
scores_kernel(const bf16* q_h, const bf16* q_l,
              const bf16* k_h, const bf16* k_l, float* __restrict__ S)
{
    extern __shared__ __align__(128) char smem[];
    const int z = blockIdx.z;
    const int m0 = blockIdx.y * 64;
    const int n0 = blockIdx.x * 256;

    float acc[2][8][4];
    #pragma unroll
    for (int i = 0; i < 2; i++)
        #pragma unroll
        for (int j = 0; j < 8; j++)
            #pragma unroll
            for (int e = 0; e < 4; e++) acc[i][j][e] = 0.f;

    gemm_mainloop<2, 3, false>(
        (const uint16_t*)q_h, (const uint16_t*)q_l,
        (const uint16_t*)k_h, (const uint16_t*)k_l,
        ((long long)z * SDEC + m0) * UNITS,
        ((long long)z * SENC + n0) * UNITS, UNITS, acc, smem);

    const int wid = threadIdx.x >> 5, lane = threadIdx.x & 31;
    const int rr0 = m0 + (wid >> 2) * 32 + (lane >> 2);
    const int cc0 = n0 + (wid & 3) * 64 + (lane & 3) * 2;
    float* Sb = S + (long long)z * SDEC * SENC;

    #pragma unroll
    for (int i = 0; i < 2; i++) {
        #pragma unroll
        for (int j = 0; j < 8; j++) {
            const float* a = acc[i][j];
            const int r0 = rr0 + i * 16;
            const int c  = cc0 + j * 8;
            *(float2*)(Sb + (long long)r0 * SENC + c)       = make_float2(a[0], a[1]);
            *(float2*)(Sb + (long long)(r0 + 8) * SENC + c) = make_float2(a[2], a[3]);
        }
    }
}

// ---------------------------------------------------------------------------
// PV: out[b] = P[b] @ V[b] (B operand = V^T rows). BM=128, BN=256, K=2048,
// TERMS=1 fp16. grid = (2, 8, 8)
// ---------------------------------------------------------------------------
constexpr int SMEM_PV = NST * (128 * 80 + 256 * 80);      // 92160

__global__ void __launch_bounds__(256, 1)
pv_kernel(const __half* P, const __half* VT, float* __restrict__ O)
{
    extern __shared__ __align__(128) char smem[];
    const int z = blockIdx.z;
    const int m0 = blockIdx.y * 128;
    const int n0 = blockIdx.x * 256;

    float acc[4][8][4];
    #pragma unroll
    for (int i = 0; i < 4; i++)
        #pragma unroll
        for (int j = 0; j < 8; j++)
            #pragma unroll
            for (int e = 0; e < 4; e++) acc[i][j][e] = 0.f;

    gemm_mainloop<4, 1, true>(
        (const uint16_t*)P, nullptr, (const uint16_t*)VT, nullptr,
        ((long long)z * SDEC + m0) * SENC,
        ((long long)z * UNITS + n0) * SENC, SENC, acc, smem);

    const int wid = threadIdx.x >> 5, lane = threadIdx.x & 31;
    const int rr0 = m0 + (wid >> 2) * 64 + (lane >> 2);
    const int cc0 = n0 + (wid & 3) * 64 + (lane & 3) * 2;
    float* Ob = O + (long long)z * SDEC * UNITS;

    #pragma unroll
    for (int i = 0; i < 4; i++) {
        #pragma unroll
        for (int j = 0; j < 8; j++) {
            const float* a = acc[i][j];
            const int r0 = rr0 + i * 16;
            const int c  = cc0 + j * 8;
            *(float2*)(Ob + (long long)r0 * UNITS + c)       = make_float2(a[0], a[1]);
            *(float2*)(Ob + (long long)(r0 + 8) * UNITS + c) = make_float2(a[2], a[3]);
        }
    }
}

// ---------------------------------------------------------------------------
// fp32 -> bf16 hi/lo split (vectorized)
// ---------------------------------------------------------------------------
__global__ void __launch_bounds__(256)
split4_kernel(const float4* __restrict__ X, __nv_bfloat162* __restrict__ hi,
              __nv_bfloat162* __restrict__ lo, int n4)
{
    int i = blockIdx.x * blockDim.x + threadIdx.x;
    if (i >= n4) return;
    float4 v = X[i];
    bf16 h0,l0,h1,l1,h2,l2,h3,l3;
    split2(v.x,h0,l0); split2(v.y,h1,l1); split2(v.z,h2,l2); split2(v.w,h3,l3);
    hi[2*i]   = __nv_bfloat162(h0,h1);
    hi[2*i+1] = __nv_bfloat162(h2,h3);
    lo[2*i]   = __nv_bfloat162(l0,l1);
    lo[2*i+1] = __nv_bfloat162(l2,l3);
}

// W [K,N] fp32 -> W^T hi/lo [N,K] bf16
__global__ void __launch_bounds__(256)
splitT512_kernel(const float* __restrict__ W, bf16* __restrict__ ht,
                 bf16* __restrict__ lt)
{
    int idx = blockIdx.x * 256 + threadIdx.x;
    int k = idx >> 9, n = idx & 511;
    bf16 h, l; split2(W[idx], h, l);
    ht[n * 512 + k] = h;
    lt[n * 512 + k] = l;
}

// ---------------------------------------------------------------------------
// Row softmax over 2048 fp32 scores -> fp16 probabilities
// ---------------------------------------------------------------------------
__inline__ __device__ float warpMax(float v) {
    #pragma unroll
    for (int o = 16; o; o >>= 1) v = fmaxf(v, __shfl_xor_sync(0xffffffffu, v, o));
    return v;
}
__inline__ __device__ float warpSum(float v) {
    #pragma unroll
    for (int o = 16; o; o >>= 1) v += __shfl_xor_sync(0xffffffffu, v, o);
    return v;
}

__global__ void __launch_bounds__(256)
softmax_h(const float* __restrict__ S, __half* __restrict__ P)
{
    const long long row = blockIdx.x;
    const float4* p = (const float4*)(S + row * (long long)SENC);
    const int tid = threadIdx.x, lane = tid & 31, wid = tid >> 5;

    float4 v0 = p[tid];
    float4 v1 = p[tid + 256];

    float m = fmaxf(fmaxf(fmaxf(v0.x, v0.y), fmaxf(v0.z, v0.w)),
                    fmaxf(fmaxf(v1.x, v1.y), fmaxf(v1.z, v1.w)));
    __shared__ float smax[8], ssum[8];
    m = warpMax(m);
    if (lane == 0) smax[wid] = m;
    __syncthreads();
    float bm = smax[0];
    #pragma unroll
    for (int i = 1; i < 8; i++) bm = fmaxf(bm, smax[i]);

    v0.x = __expf(v0.x - bm); v0.y = __expf(v0.y - bm);
    v0.z = __expf(v0.z - bm); v0.w = __expf(v0.w - bm);
    v1.x = __expf(v1.x - bm); v1.y = __expf(v1.y - bm);
    v1.z = __expf(v1.z - bm); v1.w = __expf(v1.w - bm);

    float s = (v0.x + v0.y + v0.z + v0.w) + (v1.x + v1.y + v1.z + v1.w);
    s = warpSum(s);
    if (lane == 0) ssum[wid] = s;
    __syncthreads();
    float bs = 0.f;
    #pragma unroll
    for (int i = 0; i < 8; i++) bs += ssum[i];
    const float inv = 1.0f / bs;

    __half2* ph = (__half2*)(P + row * (long long)SENC);
    ph[2*tid]         = __floats2half2_rn(v0.x * inv, v0.y * inv);
    ph[2*tid+1]       = __floats2half2_rn(v0.z * inv, v0.w * inv);
    ph[512 + 2*tid]   = __floats2half2_rn(v1.x * inv, v1.y * inv);
    ph[512 + 2*tid+1] = __floats2half2_rn(v1.z * inv, v1.w * inv);
}

// ---------------------------------------------------------------------------
extern "C" void kernel_launch(void* const* d_in, const int* in_sizes, int n_in,
                              void* d_out, int out_size)
{
    const float* enc = (const float*)d_in[0];
    const float* dec = (const float*)d_in[1];
    const float* Wq  = (const float*)d_in[2];
    const float* Wk  = (const float*)d_in[3];
    const float* Wv  = (const float*)d_in[4];
    float* out = (float*)d_out;

    bf16 *dec_h,*dec_l,*enc_h,*enc_l,*wqT_h,*wqT_l,*wkT_h,*wkT_l,*wvT_h,*wvT_l;
    bf16 *q_h,*q_l,*k_h,*k_l;
    __half *vt16, *p16;
    float *s;
    cudaGetSymbolAddress((void**)&dec_h, g_dec_h);
    cudaGetSymbolAddress((void**)&dec_l, g_dec_l);
    cudaGetSymbolAddress((void**)&enc_h, g_enc_h);
    cudaGetSymbolAddress((void**)&enc_l, g_enc_l);
    cudaGetSymbolAddress((void**)&wqT_h, g_wqT_h);
    cudaGetSymbolAddress((void**)&wqT_l, g_wqT_l);
    cudaGetSymbolAddress((void**)&wkT_h, g_wkT_h);
    cudaGetSymbolAddress((void**)&wkT_l, g_wkT_l);
    cudaGetSymbolAddress((void**)&wvT_h, g_wvT_h);
    cudaGetSymbolAddress((void**)&wvT_l, g_wvT_l);
    cudaGetSymbolAddress((void**)&q_h, g_q_h);
    cudaGetSymbolAddress((void**)&q_l, g_q_l);
    cudaGetSymbolAddress((void**)&k_h, g_k_h);
    cudaGetSymbolAddress((void**)&k_l, g_k_l);
    cudaGetSymbolAddress((void**)&vt16, g_vt16);
    cudaGetSymbolAddress((void**)&p16, g_p16);
    cudaGetSymbolAddress((void**)&s, g_s);

    cudaFuncSetAttribute(proj_kernel,   cudaFuncAttributeMaxDynamicSharedMemorySize, SMEM_P3);
    cudaFuncSetAttribute(scores_kernel, cudaFuncAttributeMaxDynamicSharedMemorySize, SMEM_P3);
    cudaFuncSetAttribute(pv_kernel,     cudaFuncAttributeMaxDynamicSharedMemorySize, SMEM_PV);

    // 1. input splits
    {
        int n4 = NB * SDEC * DIN / 4;
        split4_kernel<<<(n4 + 255) / 256, 256>>>(
            (const float4*)dec, (__nv_bfloat162*)dec_h, (__nv_bfloat162*)dec_l, n4);
    }
    {
        int n4 = NB * SENC * DIN / 4;
        split4_kernel<<<(n4 + 255) / 256, 256>>>(
            (const float4*)enc, (__nv_bfloat162*)enc_h, (__nv_bfloat162*)enc_l, n4);
    }
    splitT512_kernel<<<1024, 256>>>(Wq, wqT_h, wqT_l);
    splitT512_kernel<<<1024, 256>>>(Wk, wkT_h, wkT_l);
    splitT512_kernel<<<1024, 256>>>(Wv, wvT_h, wvT_l);

    // 2. merged projections (Q, K, V^T)
    proj_kernel<<<dim3(2, 640, 1), 256, SMEM_P3>>>(
        dec_h, dec_l, enc_h, enc_l,
        wqT_h, wqT_l, wkT_h, wkT_l, wvT_h, wvT_l,
        q_h, q_l, k_h, k_l, vt16);

    // 3. scores
    scores_kernel<<<dim3(8, 16, 8), 256, SMEM_P3>>>(q_h, q_l, k_h, k_l, s);

    // 4. softmax -> fp16 P
    softmax_h<<<NB * SDEC, 256>>>(s, p16);

    // 5. out = P @ V (fp16 single-term)
    pv_kernel<<<dim3(2, 8, 8), 256, SMEM_PV>>>(p16, vt16, out);
}

// round 6
// speedup vs baseline: 3.4789x; 1.2708x over previous
#include <cuda_runtime.h>
#include <cuda_bf16.h>
#include <cuda_fp16.h>
#include <cstdint>

#define NB    8
#define SENC  2048
#define SDEC  1024
#define DIN   512
#define UNITS 512

using bf16 = __nv_bfloat16;

// ---------------------------------------------------------------------------
// Scratch (__device__ globals: allocation-free rule)
// ---------------------------------------------------------------------------
__device__ __align__(256) bf16 g_dec_h[(size_t)NB * SDEC * DIN];
__device__ __align__(256) bf16 g_dec_l[(size_t)NB * SDEC * DIN];
__device__ __align__(256) bf16 g_enc_h[(size_t)NB * SENC * DIN];
__device__ __align__(256) bf16 g_enc_l[(size_t)NB * SENC * DIN];
__device__ __align__(256) bf16 g_wvT_h[DIN * UNITS];
__device__ __align__(256) bf16 g_wvT_l[DIN * UNITS];
__device__ __align__(256) bf16 g_mt_h[DIN * DIN];      // MT[e][d] = (Wq Wk^T)^T
__device__ __align__(256) bf16 g_mt_l[DIN * DIN];
__device__ __align__(256) bf16 g_t_h[(size_t)NB * SDEC * DIN];   // T = dec*M
__device__ __align__(256) bf16 g_t_l[(size_t)NB * SDEC * DIN];
__device__ __align__(256) __half g_vt16[(size_t)NB * UNITS * SENC]; // V^T fp16
__device__ __align__(256) float g_s[(size_t)NB * SDEC * SENC];      // fp32 scores
__device__ __align__(256) __half g_p16[(size_t)NB * SDEC * SENC];   // P fp16

// ---------------------------------------------------------------------------
// helpers
// ---------------------------------------------------------------------------
__device__ __forceinline__ void split2(float x, bf16& h, bf16& l) {
    h = __float2bfloat16(x);
    l = __float2bfloat16(x - __bfloat162float(h));
}

#define CPA(dst, src) asm volatile( \
    "cp.async.cg.shared.global [%0], [%1], 16;" :: "r"(dst), "l"(src))
#define CP_COMMIT() asm volatile("cp.async.commit_group;")
#define CP_WAIT2()  asm volatile("cp.async.wait_group 2;")

#define LDSM4(r0,r1,r2,r3,addr) asm volatile( \
    "ldmatrix.sync.aligned.m8n8.x4.shared.b16 {%0,%1,%2,%3}, [%4];" \
    : "=r"(r0),"=r"(r1),"=r"(r2),"=r"(r3) : "r"(addr))

#define MMA_BF16(ac,Af,B0,B1) asm volatile( \
    "mma.sync.aligned.m16n8k16.row.col.f32.bf16.bf16.f32 " \
    "{%0,%1,%2,%3}, {%4,%5,%6,%7}, {%8,%9}, {%0,%1,%2,%3};" \
    : "+f"(ac[0]),"+f"(ac[1]),"+f"(ac[2]),"+f"(ac[3]) \
    : "r"(Af[0]),"r"(Af[1]),"r"(Af[2]),"r"(Af[3]), "r"(B0),"r"(B1))

#define MMA_FP16(ac,Af,B0,B1) asm volatile( \
    "mma.sync.aligned.m16n8k16.row.col.f32.f16.f16.f32 " \
    "{%0,%1,%2,%3}, {%4,%5,%6,%7}, {%8,%9}, {%0,%1,%2,%3};" \
    : "+f"(ac[0]),"+f"(ac[1]),"+f"(ac[2]),"+f"(ac[3]) \
    : "r"(Af[0]),"r"(Af[1]),"r"(Af[2]),"r"(Af[3]), "r"(B0),"r"(B1))

// ---------------------------------------------------------------------------
// Generic NT GEMM mainloop (256 threads, 8 warps as 2x4, BN=256, BK=32).
// IM = m16 fragments per warp (BM = 32*IM). TERMS=3: bf16 2-term split.
// TERMS=1 & FP16: plain fp16. acc[IM][8][4] fp32.
// ---------------------------------------------------------------------------
constexpr int NST = 3;

template <int IM, int TERMS, bool FP16>
__device__ __forceinline__ void gemm_mainloop(
    const uint16_t* __restrict__ Ah, const uint16_t* __restrict__ Al,
    const uint16_t* __restrict__ Bh, const uint16_t* __restrict__ Bl,
    long long aBase, long long bBase, int K,
    float acc[][8][4], char* smem)
{
    constexpr int BM   = 32 * IM;
    constexpr int A_TB = BM * 80;       // bytes per A tile (LDK=40 pitch)
    constexpr int B_TB = 256 * 80;
    constexpr int BOFF = (TERMS == 3) ? 2 * A_TB : A_TB;
    constexpr int STG  = (TERMS == 3) ? 2 * (A_TB + B_TB) : (A_TB + B_TB);

    const int tid  = threadIdx.x;
    const int wid  = tid >> 5;
    const int lane = tid & 31;
    const int wm = (wid >> 2) * (BM / 2);
    const int wn = (wid & 3) * 64;

    const uint32_t sm0 = (uint32_t)__cvta_generic_to_shared(smem);

    const int a_row = (lane & 7) + ((lane >> 3) & 1) * 8;
    const int a_kad = ((lane >> 4) & 1) * 8;
    const int b_row = (lane & 7) + ((lane >> 4) & 1) * 8;
    const int b_kad = ((lane >> 3) & 1) * 8;

    const int nk = K / 32;

    auto load_stage = [&](int s, int k0) {
        const uint32_t st = sm0 + s * STG;
        #pragma unroll
        for (int c = tid; c < BM * 4; c += 256) {
            const int row = c >> 2, col = c & 3;
            const uint32_t sa = st + row * 80 + col * 16;
            const long long g = aBase + (long long)row * K + k0 + col * 8;
            CPA(sa, Ah + g);
            if (TERMS == 3) CPA(sa + A_TB, Al + g);
        }
        #pragma unroll
        for (int c = tid; c < 1024; c += 256) {
            const int row = c >> 2, col = c & 3;
            const uint32_t sb = st + BOFF + row * 80 + col * 16;
            const long long g = bBase + (long long)row * K + k0 + col * 8;
            CPA(sb, Bh + g);
            if (TERMS == 3) CPA(sb + B_TB, Bl + g);
        }
    };

    #pragma unroll
    for (int s = 0; s < NST; s++) {
        load_stage(s, s * 32);
        CP_COMMIT();
    }

    for (int kt = 0; kt < nk; kt++) {
        CP_WAIT2();
        __syncthreads();
        const uint32_t st  = sm0 + (kt % 3) * STG;
        const uint32_t stA = st, stB = st + BOFF;

        #pragma unroll
        for (int ks = 0; ks < 2; ks++) {
            const int kk = ks * 16;
            uint32_t ah[IM][4], al[IM][4];
            #pragma unroll
            for (int i = 0; i < IM; i++) {
                const uint32_t off = ((wm + i * 16 + a_row) * 40 + kk + a_kad) * 2;
                LDSM4(ah[i][0], ah[i][1], ah[i][2], ah[i][3], stA + off);
                if (TERMS == 3)
                    LDSM4(al[i][0], al[i][1], al[i][2], al[i][3], stA + A_TB + off);
            }
            #pragma unroll
            for (int j2 = 0; j2 < 4; j2++) {
                uint32_t bh[4], bl[4];
                const uint32_t off = ((wn + j2 * 16 + b_row) * 40 + kk + b_kad) * 2;
                LDSM4(bh[0], bh[1], bh[2], bh[3], stB + off);
                if (TERMS == 3)
                    LDSM4(bl[0], bl[1], bl[2], bl[3], stB + B_TB + off);
                #pragma unroll
                for (int i = 0; i < IM; i++) {
                    if (FP16) {
                        MMA_FP16(acc[i][2*j2],   ah[i], bh[0], bh[1]);
                        MMA_FP16(acc[i][2*j2+1], ah[i], bh[2], bh[3]);
                    } else {
                        MMA_BF16(acc[i][2*j2],   ah[i], bh[0], bh[1]);
                        MMA_BF16(acc[i][2*j2+1], ah[i], bh[2], bh[3]);
                        if (TERMS == 3) {
                            MMA_BF16(acc[i][2*j2],   ah[i], bl[0], bl[1]);
                            MMA_BF16(acc[i][2*j2],   al[i], bh[0], bh[1]);
                            MMA_BF16(acc[i][2*j2+1], ah[i], bl[2], bl[3]);
                            MMA_BF16(acc[i][2*j2+1], al[i], bh[2], bh[3]);
                        }
                    }
                }
            }
        }
        __syncthreads();
        if (kt + NST < nk)
            load_stage(kt % 3, (kt + NST) * 32);
        CP_COMMIT();
    }
}

// ---------------------------------------------------------------------------
// Merged V-projection + T kernel. BM=128, BN=256, K=512, TERMS=3.
// grid (2, 192): y<128 -> V = enc*Wv (fp16 V^T epilogue)
//                else  -> T = dec*M  (split bf16 epilogue)
// ---------------------------------------------------------------------------
constexpr int SMEM_G3 = NST * 2 * (128 * 80 + 256 * 80);   // 184320
constexpr int SMEM_PV = NST * (128 * 80 + 256 * 80);       // 92160

__global__ void __launch_bounds__(256, 1)
projvt_kernel(const bf16* dec_h, const bf16* dec_l,
              const bf16* enc_h, const bf16* enc_l,
              const bf16* wv_h, const bf16* wv_l,
              const bf16* mt_h, const bf16* mt_l,
              bf16* t_h, bf16* t_l, __half* vt)
{
    extern __shared__ __align__(128) char smem[];
    const int y = blockIdx.y;
    const int n0 = blockIdx.x * 256;

    const uint16_t *Ah, *Al, *Bh, *Bl;
    int mode, arow0;
    if (y < 128) {
        Ah = (const uint16_t*)enc_h; Al = (const uint16_t*)enc_l;
        Bh = (const uint16_t*)wv_h;  Bl = (const uint16_t*)wv_l;
        mode = 2; arow0 = y * 128;
    } else {
        Ah = (const uint16_t*)dec_h; Al = (const uint16_t*)dec_l;
        Bh = (const uint16_t*)mt_h;  Bl = (const uint16_t*)mt_l;
        mode = 1; arow0 = (y - 128) * 128;
    }

    float acc[4][8][4];
    #pragma unroll
    for (int i = 0; i < 4; i++)
        #pragma unroll
        for (int j = 0; j < 8; j++)
            #pragma unroll
            for (int e = 0; e < 4; e++) acc[i][j][e] = 0.f;

    gemm_mainloop<4, 3, false>(Ah, Al, Bh, Bl,
        (long long)arow0 * DIN, (long long)n0 * DIN, DIN, acc, smem);

    const int wid = threadIdx.x >> 5, lane = threadIdx.x & 31;
    const int rr0 = arow0 + (wid >> 2) * 64 + (lane >> 2);
    const int cc0 = n0 + (wid & 3) * 64 + (lane & 3) * 2;

    #pragma unroll
    for (int i = 0; i < 4; i++) {
        #pragma unroll
        for (int j = 0; j < 8; j++) {
            const float* a = acc[i][j];
            const int r0 = rr0 + i * 16;
            const int c  = cc0 + j * 8;
            if (mode == 1) {
                bf16 h0,l0,h1,l1,h2,l2,h3,l3;
                split2(a[0],h0,l0); split2(a[1],h1,l1);
                split2(a[2],h2,l2); split2(a[3],h3,l3);
                const size_t i0 = (size_t)r0 * DIN + c;
                const size_t i1 = (size_t)(r0 + 8) * DIN + c;
                *(__nv_bfloat162*)(t_h + i0) = __nv_bfloat162(h0, h1);
                *(__nv_bfloat162*)(t_l + i0) = __nv_bfloat162(l0, l1);
                *(__nv_bfloat162*)(t_h + i1) = __nv_bfloat162(h2, h3);
                *(__nv_bfloat162*)(t_l + i1) = __nv_bfloat162(l2, l3);
            } else {
                #pragma unroll
                for (int e = 0; e < 4; e++) {
                    const int rr = r0 + (e >> 1) * 8;        // enc row
                    const int cn = c + (e & 1);              // unit
                    const size_t idx = (size_t)(rr >> 11) * ((size_t)UNITS * SENC)
                                     + (size_t)cn * SENC + (rr & 2047);
                    vt[idx] = __float2half(a[e]);
                }
            }
        }
    }
}

// ---------------------------------------------------------------------------
// Scores: S[b] = T[b] @ enc[b]^T, BM=128, BN=256, K=512, TERMS=3, fp32 out.
// grid = (8, 8, 8)
// ---------------------------------------------------------------------------
__global__ void __launch_bounds__(256, 1)
scores_kernel(const bf16* t_h, const bf16* t_l,
              const bf16* enc_h, const bf16* enc_l, float* __restrict__ S)
{
    extern __shared__ __align__(128) char smem[];
    const int z = blockIdx.z;
    const int m0 = blockIdx.y * 128;
    const int n0 = blockIdx.x * 256;

    float acc[4][8][4];
    #pragma unroll
    for (int i = 0; i < 4; i++)
        #pragma unroll
        for (int j = 0; j < 8; j++)
            #pragma unroll
            for (int e = 0; e < 4; e++) acc[i][j][e] = 0.f;

    gemm_mainloop<4, 3, false>(
        (const uint16_t*)t_h, (const uint16_t*)t_l,
        (const uint16_t*)enc_h, (const uint16_t*)enc_l,
        ((long long)z * SDEC + m0) * DIN,
        ((long long)z * SENC + n0) * DIN, DIN, acc, smem);

    const int wid = threadIdx.x >> 5, lane = threadIdx.x & 31;
    const int rr0 = m0 + (wid >> 2) * 64 + (lane >> 2);
    const int cc0 = n0 + (wid & 3) * 64 + (lane & 3) * 2;
    float* Sb = S + (long long)z * SDEC * SENC;

    #pragma unroll
    for (int i = 0; i < 4; i++) {
        #pragma unroll
        for (int j = 0; j < 8; j++) {
            const float* a = acc[i][j];
            const int r0 = rr0 + i * 16;
            const int c  = cc0 + j * 8;
            *(float2*)(Sb + (long long)r0 * SENC + c)       = make_float2(a[0], a[1]);
            *(float2*)(Sb + (long long)(r0 + 8) * SENC + c) = make_float2(a[2], a[3]);
        }
    }
}

// ---------------------------------------------------------------------------
// PV: out[b] = P[b] @ V[b]. BM=128, BN=256, K=2048, fp16. grid (2, 8, 8)
// ---------------------------------------------------------------------------
__global__ void __launch_bounds__(256, 1)
pv_kernel(const __half* P, const __half* VT, float* __restrict__ O)
{
    extern __shared__ __align__(128) char smem[];
    const int z = blockIdx.z;
    const int m0 = blockIdx.y * 128;
    const int n0 = blockIdx.x * 256;

    float acc[4][8][4];
    #pragma unroll
    for (int i = 0; i < 4; i++)
        #pragma unroll
        for (int j = 0; j < 8; j++)
            #pragma unroll
            for (int e = 0; e < 4; e++) acc[i][j][e] = 0.f;

    gemm_mainloop<4, 1, true>(
        (const uint16_t*)P, nullptr, (const uint16_t*)VT, nullptr,
        ((long long)z * SDEC + m0) * SENC,
        ((long long)z * UNITS + n0) * SENC, SENC, acc, smem);

    const int wid = threadIdx.x >> 5, lane = threadIdx.x & 31;
    const int rr0 = m0 + (wid >> 2) * 64 + (lane >> 2);
    const int cc0 = n0 + (wid & 3) * 64 + (lane & 3) * 2;
    float* Ob = O + (long long)z * SDEC * UNITS;

    #pragma unroll
    for (int i = 0; i < 4; i++) {
        #pragma unroll
        for (int j = 0; j < 8; j++) {
            const float* a = acc[i][j];
            const int r0 = rr0 + i * 16;
            const int c  = cc0 + j * 8;
            *(float2*)(Ob + (long long)r0 * UNITS + c)       = make_float2(a[0], a[1]);
            *(float2*)(Ob + (long long)(r0 + 8) * UNITS + c) = make_float2(a[2], a[3]);
        }
    }
}

// ---------------------------------------------------------------------------
// MT = Wk * Wq^T (fp32 SIMT, exact), split-bf16 output. 32x32 tiles, grid 16x16.
// MT[e][d] = sum_u Wk[e*512+u] * Wq[d*512+u]
// ---------------------------------------------------------------------------
__global__ void __launch_bounds__(256)
mgemm_kernel(const float* __restrict__ Wk, const float* __restrict__ Wq,
             bf16* __restrict__ mh, bf16* __restrict__ ml)
{
    __shared__ float As[16][36];
    __shared__ float Bs[16][36];
    const int e0 = blockIdx.y * 32, d0 = blockIdx.x * 32;
    const int tid = threadIdx.x;
    const int ty = tid >> 4, tx = tid & 15;

    float c00 = 0.f, c01 = 0.f, c10 = 0.f, c11 = 0.f;

    for (int u0 = 0; u0 < 512; u0 += 16) {
        {
            const int t = tid & 127;
            const int row = t >> 2, col = (t & 3) * 4;
            if (tid < 128) {
                float4 a = *(const float4*)(Wk + (size_t)(e0 + row) * 512 + u0 + col);
                As[col+0][row] = a.x; As[col+1][row] = a.y;
                As[col+2][row] = a.z; As[col+3][row] = a.w;
            } else {
                float4 b = *(const float4*)(Wq + (size_t)(d0 + row) * 512 + u0 + col);
                Bs[col+0][row] = b.x; Bs[col+1][row] = b.y;
                Bs[col+2][row] = b.z; Bs[col+3][row] = b.w;
            }
        }
        __syncthreads();
        #pragma unroll
        for (int k = 0; k < 16; k++) {
            float a0 = As[k][ty*2], a1 = As[k][ty*2+1];
            float b0 = Bs[k][tx*2], b1 = Bs[k][tx*2+1];
            c00 += a0*b0; c01 += a0*b1; c10 += a1*b0; c11 += a1*b1;
        }
        __syncthreads();
    }
    bf16 h, l;
    size_t i0 = (size_t)(e0 + ty*2) * 512 + d0 + tx*2;
    size_t i1 = i0 + 512;
    split2(c00, h, l); mh[i0]   = h; ml[i0]   = l;
    split2(c01, h, l); mh[i0+1] = h; ml[i0+1] = l;
    split2(c10, h, l); mh[i1]   = h; ml[i1]   = l;
    split2(c11, h, l); mh[i1+1] = h; ml[i1+1] = l;
}

// ---------------------------------------------------------------------------
// One merged split kernel: dec -> hi/lo, enc -> hi/lo, Wv -> W^T hi/lo
// blocks: [0,4096) dec f4 | [4096,12288) enc f4 | [12288,13312) WvT scalar
// ---------------------------------------------------------------------------
__global__ void __launch_bounds__(256)
split_all_kernel(const float4* __restrict__ dec, const float4* __restrict__ enc,
                 const float* __restrict__ Wv,
                 __nv_bfloat162* __restrict__ dh, __nv_bfloat162* __restrict__ dl,
                 __nv_bfloat162* __restrict__ eh, __nv_bfloat162* __restrict__ el,
                 bf16* __restrict__ vh, bf16* __restrict__ vl)
{
    const int b = blockIdx.x;
    if (b < 12288) {
        const float4* X; __nv_bfloat162 *hi, *lo; int i;
        if (b < 4096) { X = dec; hi = dh; lo = dl; i = b * 256 + threadIdx.x; }
        else          { X = enc; hi = eh; lo = el; i = (b - 4096) * 256 + threadIdx.x; }
        float4 v = X[i];
        bf16 h0,l0,h1,l1,h2,l2,h3,l3;
        split2(v.x,h0,l0); split2(v.y,h1,l1); split2(v.z,h2,l2); split2(v.w,h3,l3);
        hi[2*i]   = __nv_bfloat162(h0,h1);
        hi[2*i+1] = __nv_bfloat162(h2,h3);
        lo[2*i]   = __nv_bfloat162(l0,l1);
        lo[2*i+1] = __nv_bfloat162(l2,l3);
    } else {
        int idx = (b - 12288) * 256 + threadIdx.x;   // [0, 262144)
        int k = idx >> 9, n = idx & 511;
        bf16 h, l; split2(Wv[idx], h, l);
        vh[n * 512 + k] = h;
        vl[n * 512 + k] = l;
    }
}

// ---------------------------------------------------------------------------
// Row softmax over 2048 fp32 scores -> fp16 probabilities
// ---------------------------------------------------------------------------
__inline__ __device__ float warpMax(float v) {
    #pragma unroll
    for (int o = 16; o; o >>= 1) v = fmaxf(v, __shfl_xor_sync(0xffffffffu, v, o));
    return v;
}
__inline__ __device__ float warpSum(float v) {
    #pragma unroll
    for (int o = 16; o; o >>= 1) v += __shfl_xor_sync(0xffffffffu, v, o);
    return v;
}

__global__ void __launch_bounds__(256)
softmax_h(const float* __restrict__ S, __half* __restrict__ P)
{
    const long long row = blockIdx.x;
    const float4* p = (const float4*)(S + row * (long long)SENC);
    const int tid = threadIdx.x, lane = tid & 31, wid = tid >> 5;

    float4 v0 = p[tid];
    float4 v1 = p[tid + 256];

    float m = fmaxf(fmaxf(fmaxf(v0.x, v0.y), fmaxf(v0.z, v0.w)),
                    fmaxf(fmaxf(v1.x, v1.y), fmaxf(v1.z, v1.w)));
    __shared__ float smax[8], ssum[8];
    m = warpMax(m);
    if (lane == 0) smax[wid] = m;
    __syncthreads();
    float bm = smax[0];
    #pragma unroll
    for (int i = 1; i < 8; i++) bm = fmaxf(bm, smax[i]);

    v0.x = __expf(v0.x - bm); v0.y = __expf(v0.y - bm);
    v0.z = __expf(v0.z - bm); v0.w = __expf(v0.w - bm);
    v1.x = __expf(v1.x - bm); v1.y = __expf(v1.y - bm);
    v1.z = __expf(v1.z - bm); v1.w = __expf(v1.w - bm);

    float s = (v0.x + v0.y + v0.z + v0.w) + (v1.x + v1.y + v1.z + v1.w);
    s = warpSum(s);
    if (lane == 0) ssum[wid] = s;
    __syncthreads();
    float bs = 0.f;
    #pragma unroll
    for (int i = 0; i < 8; i++) bs += ssum[i];
    const float inv = 1.0f / bs;

    __half2* ph = (__half2*)(P + row * (long long)SENC);
    ph[2*tid]         = __floats2half2_rn(v0.x * inv, v0.y * inv);
    ph[2*tid+1]       = __floats2half2_rn(v0.z * inv, v0.w * inv);
    ph[512 + 2*tid]   = __floats2half2_rn(v1.x * inv, v1.y * inv);
    ph[512 + 2*tid+1] = __floats2half2_rn(v1.z * inv, v1.w * inv);
}

// ---------------------------------------------------------------------------
extern "C" void kernel_launch(void* const* d_in, const int* in_sizes, int n_in,
                              void* d_out, int out_size)
{
    const float* enc = (const float*)d_in[0];
    const float* dec = (const float*)d_in[1];
    const float* Wq  = (const float*)d_in[2];
    const float* Wk  = (const float*)d_in[3];
    const float* Wv  = (const float*)d_in[4];
    float* out = (float*)d_out;

    bf16 *dec_h,*dec_l,*enc_h,*enc_l,*wvT_h,*wvT_l,*mt_h,*mt_l,*t_h,*t_l;
    __half *vt16, *p16;
    float *s;
    cudaGetSymbolAddress((void**)&dec_h, g_dec_h);
    cudaGetSymbolAddress((void**)&dec_l, g_dec_l);
    cudaGetSymbolAddress((void**)&enc_h, g_enc_h);
    cudaGetSymbolAddress((void**)&enc_l, g_enc_l);
    cudaGetSymbolAddress((void**)&wvT_h, g_wvT_h);
    cudaGetSymbolAddress((void**)&wvT_l, g_wvT_l);
    cudaGetSymbolAddress((void**)&mt_h, g_mt_h);
    cudaGetSymbolAddress((void**)&mt_l, g_mt_l);
    cudaGetSymbolAddress((void**)&t_h, g_t_h);
    cudaGetSymbolAddress((void**)&t_l, g_t_l);
    cudaGetSymbolAddress((void**)&vt16, g_vt16);
    cudaGetSymbolAddress((void**)&p16, g_p16);
    cudaGetSymbolAddress((void**)&s, g_s);

    cudaFuncSetAttribute(projvt_kernel, cudaFuncAttributeMaxDynamicSharedMemorySize, SMEM_G3);
    cudaFuncSetAttribute(scores_kernel, cudaFuncAttributeMaxDynamicSharedMemorySize, SMEM_G3);
    cudaFuncSetAttribute(pv_kernel,     cudaFuncAttributeMaxDynamicSharedMemorySize, SMEM_PV);

    // 1. all input splits (dec, enc, Wv^T) in one launch
    split_all_kernel<<<13312, 256>>>(
        (const float4*)dec, (const float4*)enc, Wv,
        (__nv_bfloat162*)dec_h, (__nv_bfloat162*)dec_l,
        (__nv_bfloat162*)enc_h, (__nv_bfloat162*)enc_l,
        wvT_h, wvT_l);

    // 2. MT = Wk * Wq^T (exact fp32) -> split bf16
    mgemm_kernel<<<dim3(16, 16), 256>>>(Wk, Wq, mt_h, mt_l);

    // 3. merged V^T projection + T = dec*M
    projvt_kernel<<<dim3(2, 192), 256, SMEM_G3>>>(
        dec_h, dec_l, enc_h, enc_l, wvT_h, wvT_l, mt_h, mt_l,
        t_h, t_l, vt16);

    // 4. scores S = T @ enc^T (batched)
    scores_kernel<<<dim3(8, 8, 8), 256, SMEM_G3>>>(t_h, t_l, enc_h, enc_l, s);

    // 5. softmax -> fp16 P
    softmax_h<<<NB * SDEC, 256>>>(s, p16);

    // 6. out = P @ V
    pv_kernel<<<dim3(2, 8, 8), 256, SMEM_PV>>>(p16, vt16, out);
}

// round 7
// speedup vs baseline: 3.7607x; 1.0810x over previous
#include <cuda_runtime.h>
#include <cuda_bf16.h>
#include <cuda_fp16.h>
#include <cstdint>

#define NB    8
#define SENC  2048
#define SDEC  1024
#define DIN   512
#define UNITS 512

using bf16 = __nv_bfloat16;

// ---------------------------------------------------------------------------
// Scratch (__device__ globals: allocation-free rule)
// ---------------------------------------------------------------------------
__device__ __align__(256) bf16 g_dec_h[(size_t)NB * SDEC * DIN];
__device__ __align__(256) bf16 g_dec_l[(size_t)NB * SDEC * DIN];
__device__ __align__(256) bf16 g_enc_h[(size_t)NB * SENC * DIN];
__device__ __align__(256) bf16 g_enc_l[(size_t)NB * SENC * DIN];
__device__ __align__(256) bf16 g_wvT_h[DIN * UNITS];
__device__ __align__(256) bf16 g_wvT_l[DIN * UNITS];
__device__ __align__(256) bf16 g_mt_h[DIN * DIN];      // MT[e][d] = (Wq Wk^T)^T
__device__ __align__(256) bf16 g_mt_l[DIN * DIN];
__device__ __align__(256) bf16 g_t_h[(size_t)NB * SDEC * DIN];   // T = dec*M
__device__ __align__(256) bf16 g_t_l[(size_t)NB * SDEC * DIN];
__device__ __align__(256) __half g_vt16[(size_t)NB * UNITS * SENC]; // V^T fp16
__device__ __align__(256) float g_s[(size_t)NB * SDEC * SENC];      // fp32 scores
__device__ __align__(256) __half g_p16[(size_t)NB * SDEC * SENC];   // P fp16

// ---------------------------------------------------------------------------
// helpers
// ---------------------------------------------------------------------------
__device__ __forceinline__ void split2(float x, bf16& h, bf16& l) {
    h = __float2bfloat16(x);
    l = __float2bfloat16(x - __bfloat162float(h));
}

#define CPA(dst, src) asm volatile( \
    "cp.async.cg.shared.global [%0], [%1], 16;" :: "r"(dst), "l"(src))
#define CP_COMMIT() asm volatile("cp.async.commit_group;")

template <int N>
__device__ __forceinline__ void cp_wait() {
    asm volatile("cp.async.wait_group %0;" :: "n"(N));
}

#define LDSM4(r0,r1,r2,r3,addr) asm volatile( \
    "ldmatrix.sync.aligned.m8n8.x4.shared.b16 {%0,%1,%2,%3}, [%4];" \
    : "=r"(r0),"=r"(r1),"=r"(r2),"=r"(r3) : "r"(addr))

#define MMA_BF16(ac,Af,B0,B1) asm volatile( \
    "mma.sync.aligned.m16n8k16.row.col.f32.bf16.bf16.f32 " \
    "{%0,%1,%2,%3}, {%4,%5,%6,%7}, {%8,%9}, {%0,%1,%2,%3};" \
    : "+f"(ac[0]),"+f"(ac[1]),"+f"(ac[2]),"+f"(ac[3]) \
    : "r"(Af[0]),"r"(Af[1]),"r"(Af[2]),"r"(Af[3]), "r"(B0),"r"(B1))

#define MMA_FP16(ac,Af,B0,B1) asm volatile( \
    "mma.sync.aligned.m16n8k16.row.col.f32.f16.f16.f32 " \
    "{%0,%1,%2,%3}, {%4,%5,%6,%7}, {%8,%9}, {%0,%1,%2,%3};" \
    : "+f"(ac[0]),"+f"(ac[1]),"+f"(ac[2]),"+f"(ac[3]) \
    : "r"(Af[0]),"r"(Af[1]),"r"(Af[2]),"r"(Af[3]), "r"(B0),"r"(B1))

// ---------------------------------------------------------------------------
// Generic NT GEMM mainloop (256 threads, 8 warps as 2x4, BM=128, BN=128,
// BK=32, warp tile 64x32). TERMS=3: bf16 2-term split. TERMS=1 & FP16: fp16.
// NSTG pipeline stages. acc[4][4][4] fp32.
// ---------------------------------------------------------------------------
template <int TERMS, bool FP16, int NSTG>
__device__ __forceinline__ void gemm_mainloop(
    const uint16_t* __restrict__ Ah, const uint16_t* __restrict__ Al,
    const uint16_t* __restrict__ Bh, const uint16_t* __restrict__ Bl,
    long long aBase, long long bBase, int K,
    float acc[4][4][4], char* smem)
{
    constexpr int A_TB = 128 * 80;      // bytes per tile (LDK=40 pitch)
    constexpr int B_TB = 128 * 80;
    constexpr int BOFF = (TERMS == 3) ? 2 * A_TB : A_TB;
    constexpr int STG  = (TERMS == 3) ? 2 * (A_TB + B_TB) : (A_TB + B_TB);

    const int tid  = threadIdx.x;
    const int wid  = tid >> 5;
    const int lane = tid & 31;
    const int wm = (wid >> 2) * 64;
    const int wn = (wid & 3) * 32;

    const uint32_t sm0 = (uint32_t)__cvta_generic_to_shared(smem);

    const int a_row = (lane & 7) + ((lane >> 3) & 1) * 8;
    const int a_kad = ((lane >> 4) & 1) * 8;
    const int b_row = (lane & 7) + ((lane >> 4) & 1) * 8;
    const int b_kad = ((lane >> 3) & 1) * 8;

    const int nk = K / 32;

    auto load_stage = [&](int s, int k0) {
        const uint32_t st = sm0 + s * STG;
        #pragma unroll
        for (int c = tid; c < 512; c += 256) {
            const int row = c >> 2, col = c & 3;
            const uint32_t sa = st + row * 80 + col * 16;
            const long long g = aBase + (long long)row * K + k0 + col * 8;
            CPA(sa, Ah + g);
            if (TERMS == 3) CPA(sa + A_TB, Al + g);
        }
        #pragma unroll
        for (int c = tid; c < 512; c += 256) {
            const int row = c >> 2, col = c & 3;
            const uint32_t sb = st + BOFF + row * 80 + col * 16;
            const long long g = bBase + (long long)row * K + k0 + col * 8;
            CPA(sb, Bh + g);
            if (TERMS == 3) CPA(sb + B_TB, Bl + g);
        }
    };

    #pragma unroll
    for (int s = 0; s < NSTG; s++) {
        load_stage(s, s * 32);
        CP_COMMIT();
    }

    for (int kt = 0; kt < nk; kt++) {
        cp_wait<NSTG - 1>();
        __syncthreads();
        const uint32_t st  = sm0 + (kt % NSTG) * STG;
        const uint32_t stA = st, stB = st + BOFF;

        #pragma unroll
        for (int ks = 0; ks < 2; ks++) {
            const int kk = ks * 16;
            uint32_t ah[4][4], al[4][4];
            #pragma unroll
            for (int i = 0; i < 4; i++) {
                const uint32_t off = ((wm + i * 16 + a_row) * 40 + kk + a_kad) * 2;
                LDSM4(ah[i][0], ah[i][1], ah[i][2], ah[i][3], stA + off);
                if (TERMS == 3)
                    LDSM4(al[i][0], al[i][1], al[i][2], al[i][3], stA + A_TB + off);
            }
            #pragma unroll
            for (int j2 = 0; j2 < 2; j2++) {
                uint32_t bh[4], bl[4];
                const uint32_t off = ((wn + j2 * 16 + b_row) * 40 + kk + b_kad) * 2;
                LDSM4(bh[0], bh[1], bh[2], bh[3], stB + off);
                if (TERMS == 3)
                    LDSM4(bl[0], bl[1], bl[2], bl[3], stB + B_TB + off);
                #pragma unroll
                for (int i = 0; i < 4; i++) {
                    if (FP16) {
                        MMA_FP16(acc[i][2*j2],   ah[i], bh[0], bh[1]);
                        MMA_FP16(acc[i][2*j2+1], ah[i], bh[2], bh[3]);
                    } else {
                        MMA_BF16(acc[i][2*j2],   ah[i], bh[0], bh[1]);
                        MMA_BF16(acc[i][2*j2+1], ah[i], bh[2], bh[3]);
                        if (TERMS == 3) {
                            MMA_BF16(acc[i][2*j2],   ah[i], bl[0], bl[1]);
                            MMA_BF16(acc[i][2*j2],   al[i], bh[0], bh[1]);
                            MMA_BF16(acc[i][2*j2+1], ah[i], bl[2], bl[3]);
                            MMA_BF16(acc[i][2*j2+1], al[i], bh[2], bh[3]);
                        }
                    }
                }
            }
        }
        __syncthreads();
        if (kt + NSTG < nk)
            load_stage(kt % NSTG, (kt + NSTG) * 32);
        CP_COMMIT();
    }
}

constexpr int SMEM_G3 = 2 * 2 * (128 * 80 + 128 * 80);   // 81920 (TERMS=3, NST=2)
constexpr int SMEM_PV = 3 * (128 * 80 + 128 * 80);       // 61440 (fp16, NST=3)

// ---------------------------------------------------------------------------
// Merged V-projection + T kernel. BM=128, BN=128, K=512, TERMS=3.
// grid (4, 192): y<128 -> V = enc*Wv (fp16 V^T epilogue)
//                else  -> T = dec*M  (split bf16 epilogue)
// ---------------------------------------------------------------------------
__global__ void __launch_bounds__(256, 2)
projvt_kernel(const bf16* dec_h, const bf16* dec_l,
              const bf16* enc_h, const bf16* enc_l,
              const bf16* wv_h, const bf16* wv_l,
              const bf16* mt_h, const bf16* mt_l,
              bf16* t_h, bf16* t_l, __half* vt)
{
    extern __shared__ __align__(128) char smem[];
    const int y = blockIdx.y;
    const int n0 = blockIdx.x * 128;

    const uint16_t *Ah, *Al, *Bh, *Bl;
    int mode, arow0;
    if (y < 128) {
        Ah = (const uint16_t*)enc_h; Al = (const uint16_t*)enc_l;
        Bh = (const uint16_t*)wv_h;  Bl = (const uint16_t*)wv_l;
        mode = 2; arow0 = y * 128;
    } else {
        Ah = (const uint16_t*)dec_h; Al = (const uint16_t*)dec_l;
        Bh = (const uint16_t*)mt_h;  Bl = (const uint16_t*)mt_l;
        mode = 1; arow0 = (y - 128) * 128;
    }

    float acc[4][4][4];
    #pragma unroll
    for (int i = 0; i < 4; i++)
        #pragma unroll
        for (int j = 0; j < 4; j++)
            #pragma unroll
            for (int e = 0; e < 4; e++) acc[i][j][e] = 0.f;

    gemm_mainloop<3, false, 2>(Ah, Al, Bh, Bl,
        (long long)arow0 * DIN, (long long)n0 * DIN, DIN, acc, smem);

    const int wid = threadIdx.x >> 5, lane = threadIdx.x & 31;
    const int rr0 = arow0 + (wid >> 2) * 64 + (lane >> 2);
    const int cc0 = n0 + (wid & 3) * 32 + (lane & 3) * 2;

    #pragma unroll
    for (int i = 0; i < 4; i++) {
        #pragma unroll
        for (int j = 0; j < 4; j++) {
            const float* a = acc[i][j];
            const int r0 = rr0 + i * 16;
            const int c  = cc0 + j * 8;
            if (mode == 1) {
                bf16 h0,l0,h1,l1,h2,l2,h3,l3;
                split2(a[0],h0,l0); split2(a[1],h1,l1);
                split2(a[2],h2,l2); split2(a[3],h3,l3);
                const size_t i0 = (size_t)r0 * DIN + c;
                const size_t i1 = (size_t)(r0 + 8) * DIN + c;
                *(__nv_bfloat162*)(t_h + i0) = __nv_bfloat162(h0, h1);
                *(__nv_bfloat162*)(t_l + i0) = __nv_bfloat162(l0, l1);
                *(__nv_bfloat162*)(t_h + i1) = __nv_bfloat162(h2, h3);
                *(__nv_bfloat162*)(t_l + i1) = __nv_bfloat162(l2, l3);
            } else {
                #pragma unroll
                for (int e = 0; e < 4; e++) {
                    const int rr = r0 + (e >> 1) * 8;        // enc row
                    const int cn = c + (e & 1);              // unit
                    const size_t idx = (size_t)(rr >> 11) * ((size_t)UNITS * SENC)
                                     + (size_t)cn * SENC + (rr & 2047);
                    vt[idx] = __float2half(a[e]);
                }
            }
        }
    }
}

// ---------------------------------------------------------------------------
// Scores: S[b] = T[b] @ enc[b]^T, BM=128, BN=128, K=512, TERMS=3, fp32 out.
// grid = (16, 8, 8)
// ---------------------------------------------------------------------------
__global__ void __launch_bounds__(256, 2)
scores_kernel(const bf16* t_h, const bf16* t_l,
              const bf16* enc_h, const bf16* enc_l, float* __restrict__ S)
{
    extern __shared__ __align__(128) char smem[];
    const int z = blockIdx.z;
    const int m0 = blockIdx.y * 128;
    const int n0 = blockIdx.x * 128;

    float acc[4][4][4];
    #pragma unroll
    for (int i = 0; i < 4; i++)
        #pragma unroll
        for (int j = 0; j < 4; j++)
            #pragma unroll
            for (int e = 0; e < 4; e++) acc[i][j][e] = 0.f;

    gemm_mainloop<3, false, 2>(
        (const uint16_t*)t_h, (const uint16_t*)t_l,
        (const uint16_t*)enc_h, (const uint16_t*)enc_l,
        ((long long)z * SDEC + m0) * DIN,
        ((long long)z * SENC + n0) * DIN, DIN, acc, smem);

    const int wid = threadIdx.x >> 5, lane = threadIdx.x & 31;
    const int rr0 = m0 + (wid >> 2) * 64 + (lane >> 2);
    const int cc0 = n0 + (wid & 3) * 32 + (lane & 3) * 2;
    float* Sb = S + (long long)z * SDEC * SENC;

    #pragma unroll
    for (int i = 0; i < 4; i++) {
        #pragma unroll
        for (int j = 0; j < 4; j++) {
            const float* a = acc[i][j];
            const int r0 = rr0 + i * 16;
            const int c  = cc0 + j * 8;
            *(float2*)(Sb + (long long)r0 * SENC + c)       = make_float2(a[0], a[1]);
            *(float2*)(Sb + (long long)(r0 + 8) * SENC + c) = make_float2(a[2], a[3]);
        }
    }
}

// ---------------------------------------------------------------------------
// PV: out[b] = P[b] @ V[b]. BM=128, BN=128, K=2048, fp16. grid (4, 8, 8)
// ---------------------------------------------------------------------------
__global__ void __launch_bounds__(256, 2)
pv_kernel(const __half* P, const __half* VT, float* __restrict__ O)
{
    extern __shared__ __align__(128) char smem[];
    const int z = blockIdx.z;
    const int m0 = blockIdx.y * 128;
    const int n0 = blockIdx.x * 128;

    float acc[4][4][4];
    #pragma unroll
    for (int i = 0; i < 4; i++)
        #pragma unroll
        for (int j = 0; j < 4; j++)
            #pragma unroll
            for (int e = 0; e < 4; e++) acc[i][j][e] = 0.f;

    gemm_mainloop<1, true, 3>(
        (const uint16_t*)P, nullptr, (const uint16_t*)VT, nullptr,
        ((long long)z * SDEC + m0) * SENC,
        ((long long)z * UNITS + n0) * SENC, SENC, acc, smem);

    const int wid = threadIdx.x >> 5, lane = threadIdx.x & 31;
    const int rr0 = m0 + (wid >> 2) * 64 + (lane >> 2);
    const int cc0 = n0 + (wid & 3) * 32 + (lane & 3) * 2;
    float* Ob = O + (long long)z * SDEC * UNITS;

    #pragma unroll
    for (int i = 0; i < 4; i++) {
        #pragma unroll
        for (int j = 0; j < 4; j++) {
            const float* a = acc[i][j];
            const int r0 = rr0 + i * 16;
            const int c  = cc0 + j * 8;
            *(float2*)(Ob + (long long)r0 * UNITS + c)       = make_float2(a[0], a[1]);
            *(float2*)(Ob + (long long)(r0 + 8) * UNITS + c) = make_float2(a[2], a[3]);
        }
    }
}

// ---------------------------------------------------------------------------
// MT = Wk * Wq^T (fp32 SIMT, exact), split-bf16 output. 32x32 tiles, grid 16x16.
// ---------------------------------------------------------------------------
__global__ void __launch_bounds__(256)
mgemm_kernel(const float* __restrict__ Wk, const float* __restrict__ Wq,
             bf16* __restrict__ mh, bf16* __restrict__ ml)
{
    __shared__ float As[16][36];
    __shared__ float Bs[16][36];
    const int e0 = blockIdx.y * 32, d0 = blockIdx.x * 32;
    const int tid = threadIdx.x;
    const int ty = tid >> 4, tx = tid & 15;

    float c00 = 0.f, c01 = 0.f, c10 = 0.f, c11 = 0.f;

    for (int u0 = 0; u0 < 512; u0 += 16) {
        {
            const int t = tid & 127;
            const int row = t >> 2, col = (t & 3) * 4;
            if (tid < 128) {
                float4 a = *(const float4*)(Wk + (size_t)(e0 + row) * 512 + u0 + col);
                As[col+0][row] = a.x; As[col+1][row] = a.y;
                As[col+2][row] = a.z; As[col+3][row] = a.w;
            } else {
                float4 b = *(const float4*)(Wq + (size_t)(d0 + row) * 512 + u0 + col);
                Bs[col+0][row] = b.x; Bs[col+1][row] = b.y;
                Bs[col+2][row] = b.z; Bs[col+3][row] = b.w;
            }
        }
        __syncthreads();
        #pragma unroll
        for (int k = 0; k < 16; k++) {
            float a0 = As[k][ty*2], a1 = As[k][ty*2+1];
            float b0 = Bs[k][tx*2], b1 = Bs[k][tx*2+1];
            c00 += a0*b0; c01 += a0*b1; c10 += a1*b0; c11 += a1*b1;
        }
        __syncthreads();
    }
    bf16 h, l;
    size_t i0 = (size_t)(e0 + ty*2) * 512 + d0 + tx*2;
    size_t i1 = i0 + 512;
    split2(c00, h, l); mh[i0]   = h; ml[i0]   = l;
    split2(c01, h, l); mh[i0+1] = h; ml[i0+1] = l;
    split2(c10, h, l); mh[i1]   = h; ml[i1]   = l;
    split2(c11, h, l); mh[i1+1] = h; ml[i1+1] = l;
}

// ---------------------------------------------------------------------------
// One merged split kernel: dec -> hi/lo, enc -> hi/lo, Wv -> W^T hi/lo
// ---------------------------------------------------------------------------
__global__ void __launch_bounds__(256)
split_all_kernel(const float4* __restrict__ dec, const float4* __restrict__ enc,
                 const float* __restrict__ Wv,
                 __nv_bfloat162* __restrict__ dh, __nv_bfloat162* __restrict__ dl,
                 __nv_bfloat162* __restrict__ eh, __nv_bfloat162* __restrict__ el,
                 bf16* __restrict__ vh, bf16* __restrict__ vl)
{
    const int b = blockIdx.x;
    if (b < 12288) {
        const float4* X; __nv_bfloat162 *hi, *lo; int i;
        if (b < 4096) { X = dec; hi = dh; lo = dl; i = b * 256 + threadIdx.x; }
        else          { X = enc; hi = eh; lo = el; i = (b - 4096) * 256 + threadIdx.x; }
        float4 v = X[i];
        bf16 h0,l0,h1,l1,h2,l2,h3,l3;
        split2(v.x,h0,l0); split2(v.y,h1,l1); split2(v.z,h2,l2); split2(v.w,h3,l3);
        hi[2*i]   = __nv_bfloat162(h0,h1);
        hi[2*i+1] = __nv_bfloat162(h2,h3);
        lo[2*i]   = __nv_bfloat162(l0,l1);
        lo[2*i+1] = __nv_bfloat162(l2,l3);
    } else {
        int idx = (b - 12288) * 256 + threadIdx.x;   // [0, 262144)
        int k = idx >> 9, n = idx & 511;
        bf16 h, l; split2(Wv[idx], h, l);
        vh[n * 512 + k] = h;
        vl[n * 512 + k] = l;
    }
}

// ---------------------------------------------------------------------------
// Row softmax over 2048 fp32 scores -> fp16 probabilities
// ---------------------------------------------------------------------------
__inline__ __device__ float warpMax(float v) {
    #pragma unroll
    for (int o = 16; o; o >>= 1) v = fmaxf(v, __shfl_xor_sync(0xffffffffu, v, o));
    return v;
}
__inline__ __device__ float warpSum(float v) {
    #pragma unroll
    for (int o = 16; o; o >>= 1) v += __shfl_xor_sync(0xffffffffu, v, o);
    return v;
}

__global__ void __launch_bounds__(256)
softmax_h(const float* __restrict__ S, __half* __restrict__ P)
{
    const long long row = blockIdx.x;
    const float4* p = (const float4*)(S + row * (long long)SENC);
    const int tid = threadIdx.x, lane = tid & 31, wid = tid >> 5;

    float4 v0 = p[tid];
    float4 v1 = p[tid + 256];

    float m = fmaxf(fmaxf(fmaxf(v0.x, v0.y), fmaxf(v0.z, v0.w)),
                    fmaxf(fmaxf(v1.x, v1.y), fmaxf(v1.z, v1.w)));
    __shared__ float smax[8], ssum[8];
    m = warpMax(m);
    if (lane == 0) smax[wid] = m;
    __syncthreads();
    float bm = smax[0];
    #pragma unroll
    for (int i = 1; i < 8; i++) bm = fmaxf(bm, smax[i]);

    v0.x = __expf(v0.x - bm); v0.y = __expf(v0.y - bm);
    v0.z = __expf(v0.z - bm); v0.w = __expf(v0.w - bm);
    v1.x = __expf(v1.x - bm); v1.y = __expf(v1.y - bm);
    v1.z = __expf(v1.z - bm); v1.w = __expf(v1.w - bm);

    float s = (v0.x + v0.y + v0.z + v0.w) + (v1.x + v1.y + v1.z + v1.w);
    s = warpSum(s);
    if (lane == 0) ssum[wid] = s;
    __syncthreads();
    float bs = 0.f;
    #pragma unroll
    for (int i = 0; i < 8; i++) bs += ssum[i];
    const float inv = 1.0f / bs;

    __half2* ph = (__half2*)(P + row * (long long)SENC);
    ph[2*tid]         = __floats2half2_rn(v0.x * inv, v0.y * inv);
    ph[2*tid+1]       = __floats2half2_rn(v0.z * inv, v0.w * inv);
    ph[512 + 2*tid]   = __floats2half2_rn(v1.x * inv, v1.y * inv);
    ph[512 + 2*tid+1] = __floats2half2_rn(v1.z * inv, v1.w * inv);
}

// ---------------------------------------------------------------------------
extern "C" void kernel_launch(void* const* d_in, const int* in_sizes, int n_in,
                              void* d_out, int out_size)
{
    const float* enc = (const float*)d_in[0];
    const float* dec = (const float*)d_in[1];
    const float* Wq  = (const float*)d_in[2];
    const float* Wk  = (const float*)d_in[3];
    const float* Wv  = (const float*)d_in[4];
    float* out = (float*)d_out;

    bf16 *dec_h,*dec_l,*enc_h,*enc_l,*wvT_h,*wvT_l,*mt_h,*mt_l,*t_h,*t_l;
    __half *vt16, *p16;
    float *s;
    cudaGetSymbolAddress((void**)&dec_h, g_dec_h);
    cudaGetSymbolAddress((void**)&dec_l, g_dec_l);
    cudaGetSymbolAddress((void**)&enc_h, g_enc_h);
    cudaGetSymbolAddress((void**)&enc_l, g_enc_l);
    cudaGetSymbolAddress((void**)&wvT_h, g_wvT_h);
    cudaGetSymbolAddress((void**)&wvT_l, g_wvT_l);
    cudaGetSymbolAddress((void**)&mt_h, g_mt_h);
    cudaGetSymbolAddress((void**)&mt_l, g_mt_l);
    cudaGetSymbolAddress((void**)&t_h, g_t_h);
    cudaGetSymbolAddress((void**)&t_l, g_t_l);
    cudaGetSymbolAddress((void**)&vt16, g_vt16);
    cudaGetSymbolAddress((void**)&p16, g_p16);
    cudaGetSymbolAddress((void**)&s, g_s);

    cudaFuncSetAttribute(projvt_kernel, cudaFuncAttributeMaxDynamicSharedMemorySize, SMEM_G3);
    cudaFuncSetAttribute(scores_kernel, cudaFuncAttributeMaxDynamicSharedMemorySize, SMEM_G3);
    cudaFuncSetAttribute(pv_kernel,     cudaFuncAttributeMaxDynamicSharedMemorySize, SMEM_PV);

    // 1. all input splits (dec, enc, Wv^T) in one launch
    split_all_kernel<<<13312, 256>>>(
        (const float4*)dec, (const float4*)enc, Wv,
        (__nv_bfloat162*)dec_h, (__nv_bfloat162*)dec_l,
        (__nv_bfloat162*)enc_h, (__nv_bfloat162*)enc_l,
        wvT_h, wvT_l);

    // 2. MT = Wk * Wq^T (exact fp32) -> split bf16
    mgemm_kernel<<<dim3(16, 16), 256>>>(Wk, Wq, mt_h, mt_l);

    // 3. merged V^T projection + T = dec*M
    projvt_kernel<<<dim3(4, 192), 256, SMEM_G3>>>(
        dec_h, dec_l, enc_h, enc_l, wvT_h, wvT_l, mt_h, mt_l,
        t_h, t_l, vt16);

    // 4. scores S = T @ enc^T (batched)
    scores_kernel<<<dim3(16, 8, 8), 256, SMEM_G3>>>(t_h, t_l, enc_h, enc_l, s);

    // 5. softmax -> fp16 P
    softmax_h<<<NB * SDEC, 256>>>(s, p16);

    // 6. out = P @ V
    pv_kernel<<<dim3(4, 8, 8), 256, SMEM_PV>>>(p16, vt16, out);
}

// round 8
// speedup vs baseline: 3.8899x; 1.0344x over previous
#include <cuda_runtime.h>
#include <cuda_bf16.h>
#include <cuda_fp16.h>
#include <cstdint>

#define NB    8
#define SENC  2048
#define SDEC  1024
#define DIN   512
#define UNITS 512

using bf16 = __nv_bfloat16;

// ---------------------------------------------------------------------------
// Scratch (__device__ globals: allocation-free rule)
// ---------------------------------------------------------------------------
__device__ __align__(256) bf16 g_dec_h[(size_t)NB * SDEC * DIN];
__device__ __align__(256) bf16 g_dec_l[(size_t)NB * SDEC * DIN];
__device__ __align__(256) bf16 g_enc_h[(size_t)NB * SENC * DIN];
__device__ __align__(256) bf16 g_enc_l[(size_t)NB * SENC * DIN];
__device__ __align__(256) bf16 g_wvT_h[DIN * UNITS];
__device__ __align__(256) bf16 g_wvT_l[DIN * UNITS];
__device__ __align__(256) bf16 g_mt_h[DIN * DIN];      // MT[e][d] = (Wq Wk^T)^T
__device__ __align__(256) bf16 g_mt_l[DIN * DIN];
__device__ __align__(256) bf16 g_t_h[(size_t)NB * SDEC * DIN];   // T = dec*M
__device__ __align__(256) bf16 g_t_l[(size_t)NB * SDEC * DIN];
__device__ __align__(256) __half g_vt16[(size_t)NB * UNITS * SENC]; // V^T fp16
__device__ __align__(256) float g_s[(size_t)NB * SDEC * SENC];      // fp32 scores
__device__ __align__(256) __half g_p16[(size_t)NB * SDEC * SENC];   // P fp16

// ---------------------------------------------------------------------------
// helpers
// ---------------------------------------------------------------------------
__device__ __forceinline__ void split2(float x, bf16& h, bf16& l) {
    h = __float2bfloat16(x);
    l = __float2bfloat16(x - __bfloat162float(h));
}

#define CPA(dst, src) asm volatile( \
    "cp.async.cg.shared.global [%0], [%1], 16;" :: "r"(dst), "l"(src))
#define CP_COMMIT() asm volatile("cp.async.commit_group;")

template <int N>
__device__ __forceinline__ void cp_wait() {
    asm volatile("cp.async.wait_group %0;" :: "n"(N));
}

#define LDSM4(r0,r1,r2,r3,addr) asm volatile( \
    "ldmatrix.sync.aligned.m8n8.x4.shared.b16 {%0,%1,%2,%3}, [%4];" \
    : "=r"(r0),"=r"(r1),"=r"(r2),"=r"(r3) : "r"(addr))

#define MMA_BF16(ac,Af,B0,B1) asm volatile( \
    "mma.sync.aligned.m16n8k16.row.col.f32.bf16.bf16.f32 " \
    "{%0,%1,%2,%3}, {%4,%5,%6,%7}, {%8,%9}, {%0,%1,%2,%3};" \
    : "+f"(ac[0]),"+f"(ac[1]),"+f"(ac[2]),"+f"(ac[3]) \
    : "r"(Af[0]),"r"(Af[1]),"r"(Af[2]),"r"(Af[3]), "r"(B0),"r"(B1))

#define MMA_FP16(ac,Af,B0,B1) asm volatile( \
    "mma.sync.aligned.m16n8k16.row.col.f32.f16.f16.f32 " \
    "{%0,%1,%2,%3}, {%4,%5,%6,%7}, {%8,%9}, {%0,%1,%2,%3};" \
    : "+f"(ac[0]),"+f"(ac[1]),"+f"(ac[2]),"+f"(ac[3]) \
    : "r"(Af[0]),"r"(Af[1]),"r"(Af[2]),"r"(Af[3]), "r"(B0),"r"(B1))

// ---------------------------------------------------------------------------
// Generic NT GEMM mainloop (256 threads, 8 warps as 2x4, BM=128, BN=128,
// BK=32, warp tile 64x32). TERMS=3: bf16 2-term split. TERMS=1 & FP16: fp16.
// Single-sync software pipeline: per iteration
//   wait<NSTG-2> ; __syncthreads ; issue loads for stage kt+NSTG-1 ; compute.
// ---------------------------------------------------------------------------
template <int TERMS, bool FP16, int NSTG>
__device__ __forceinline__ void gemm_mainloop(
    const uint16_t* __restrict__ Ah, const uint16_t* __restrict__ Al,
    const uint16_t* __restrict__ Bh, const uint16_t* __restrict__ Bl,
    long long aBase, long long bBase, int K,
    float acc[4][4][4], char* smem)
{
    constexpr int A_TB = 128 * 80;      // bytes per tile (LDK=40 pitch)
    constexpr int B_TB = 128 * 80;
    constexpr int BOFF = (TERMS == 3) ? 2 * A_TB : A_TB;
    constexpr int STG  = (TERMS == 3) ? 2 * (A_TB + B_TB) : (A_TB + B_TB);

    const int tid  = threadIdx.x;
    const int wid  = tid >> 5;
    const int lane = tid & 31;
    const int wm = (wid >> 2) * 64;
    const int wn = (wid & 3) * 32;

    const uint32_t sm0 = (uint32_t)__cvta_generic_to_shared(smem);

    const int a_row = (lane & 7) + ((lane >> 3) & 1) * 8;
    const int a_kad = ((lane >> 4) & 1) * 8;
    const int b_row = (lane & 7) + ((lane >> 4) & 1) * 8;
    const int b_kad = ((lane >> 3) & 1) * 8;

    const int nk = K / 32;

    auto load_stage = [&](int s, int k0) {
        const uint32_t st = sm0 + s * STG;
        #pragma unroll
        for (int c = tid; c < 512; c += 256) {
            const int row = c >> 2, col = c & 3;
            const uint32_t sa = st + row * 80 + col * 16;
            const long long g = aBase + (long long)row * K + k0 + col * 8;
            CPA(sa, Ah + g);
            if (TERMS == 3) CPA(sa + A_TB, Al + g);
        }
        #pragma unroll
        for (int c = tid; c < 512; c += 256) {
            const int row = c >> 2, col = c & 3;
            const uint32_t sb = st + BOFF + row * 80 + col * 16;
            const long long g = bBase + (long long)row * K + k0 + col * 8;
            CPA(sb, Bh + g);
            if (TERMS == 3) CPA(sb + B_TB, Bl + g);
        }
    };

    // prologue: NSTG-1 stages in flight
    #pragma unroll
    for (int s = 0; s < NSTG - 1; s++) {
        load_stage(s, s * 32);
        CP_COMMIT();
    }

    for (int kt = 0; kt < nk; kt++) {
        cp_wait<NSTG - 2>();          // stage kt's data has landed
        __syncthreads();              // publish; also frees buffer (kt-1)%NSTG

        const int knext = kt + NSTG - 1;
        if (knext < nk)
            load_stage(knext % NSTG, knext * 32);   // overlaps compute below
        CP_COMMIT();

        const uint32_t st  = sm0 + (kt % NSTG) * STG;
        const uint32_t stA = st, stB = st + BOFF;

        #pragma unroll
        for (int ks = 0; ks < 2; ks++) {
            const int kk = ks * 16;
            uint32_t ah[4][4], al[4][4];
            #pragma unroll
            for (int i = 0; i < 4; i++) {
                const uint32_t off = ((wm + i * 16 + a_row) * 40 + kk + a_kad) * 2;
                LDSM4(ah[i][0], ah[i][1], ah[i][2], ah[i][3], stA + off);
                if (TERMS == 3)
                    LDSM4(al[i][0], al[i][1], al[i][2], al[i][3], stA + A_TB + off);
            }
            #pragma unroll
            for (int j2 = 0; j2 < 2; j2++) {
                uint32_t bh[4], bl[4];
                const uint32_t off = ((wn + j2 * 16 + b_row) * 40 + kk + b_kad) * 2;
                LDSM4(bh[0], bh[1], bh[2], bh[3], stB + off);
                if (TERMS == 3)
                    LDSM4(bl[0], bl[1], bl[2], bl[3], stB + B_TB + off);
                #pragma unroll
                for (int i = 0; i < 4; i++) {
                    if (FP16) {
                        MMA_FP16(acc[i][2*j2],   ah[i], bh[0], bh[1]);
                        MMA_FP16(acc[i][2*j2+1], ah[i], bh[2], bh[3]);
                    } else {
                        MMA_BF16(acc[i][2*j2],   ah[i], bh[0], bh[1]);
                        MMA_BF16(acc[i][2*j2+1], ah[i], bh[2], bh[3]);
                        if (TERMS == 3) {
                            MMA_BF16(acc[i][2*j2],   ah[i], bl[0], bl[1]);
                            MMA_BF16(acc[i][2*j2],   al[i], bh[0], bh[1]);
                            MMA_BF16(acc[i][2*j2+1], ah[i], bl[2], bl[3]);
                            MMA_BF16(acc[i][2*j2+1], al[i], bh[2], bh[3]);
                        }
                    }
                }
            }
        }
    }
    // NOTE: no trailing sync needed; caller epilogues only touch registers/gmem.
}

constexpr int SMEM_G3 = 2 * 2 * (128 * 80 + 128 * 80);   // 81920 (TERMS=3, NST=2)
constexpr int SMEM_PV = 4 * (128 * 80 + 128 * 80);       // 81920 (fp16, NST=4)

// ---------------------------------------------------------------------------
// Merged V-projection + T kernel. BM=128, BN=128, K=512, TERMS=3.
// grid (4, 192): y<128 -> V = enc*Wv (fp16 V^T epilogue)
//                else  -> T = dec*M  (split bf16 epilogue)
// ---------------------------------------------------------------------------
__global__ void __launch_bounds__(256, 2)
projvt_kernel(const bf16* dec_h, const bf16* dec_l,
              const bf16* enc_h, const bf16* enc_l,
              const bf16* wv_h, const bf16* wv_l,
              const bf16* mt_h, const bf16* mt_l,
              bf16* t_h, bf16* t_l, __half* vt)
{
    extern __shared__ __align__(128) char smem[];
    const int y = blockIdx.y;
    const int n0 = blockIdx.x * 128;

    const uint16_t *Ah, *Al, *Bh, *Bl;
    int mode, arow0;
    if (y < 128) {
        Ah = (const uint16_t*)enc_h; Al = (const uint16_t*)enc_l;
        Bh = (const uint16_t*)wv_h;  Bl = (const uint16_t*)wv_l;
        mode = 2; arow0 = y * 128;
    } else {
        Ah = (const uint16_t*)dec_h; Al = (const uint16_t*)dec_l;
        Bh = (const uint16_t*)mt_h;  Bl = (const uint16_t*)mt_l;
        mode = 1; arow0 = (y - 128) * 128;
    }

    float acc[4][4][4];
    #pragma unroll
    for (int i = 0; i < 4; i++)
        #pragma unroll
        for (int j = 0; j < 4; j++)
            #pragma unroll
            for (int e = 0; e < 4; e++) acc[i][j][e] = 0.f;

    gemm_mainloop<3, false, 2>(Ah, Al, Bh, Bl,
        (long long)arow0 * DIN, (long long)n0 * DIN, DIN, acc, smem);

    const int wid = threadIdx.x >> 5, lane = threadIdx.x & 31;
    const int rr0 = arow0 + (wid >> 2) * 64 + (lane >> 2);
    const int cc0 = n0 + (wid & 3) * 32 + (lane & 3) * 2;

    #pragma unroll
    for (int i = 0; i < 4; i++) {
        #pragma unroll
        for (int j = 0; j < 4; j++) {
            const float* a = acc[i][j];
            const int r0 = rr0 + i * 16;
            const int c  = cc0 + j * 8;
            if (mode == 1) {
                bf16 h0,l0,h1,l1,h2,l2,h3,l3;
                split2(a[0],h0,l0); split2(a[1],h1,l1);
                split2(a[2],h2,l2); split2(a[3],h3,l3);
                const size_t i0 = (size_t)r0 * DIN + c;
                const size_t i1 = (size_t)(r0 + 8) * DIN + c;
                *(__nv_bfloat162*)(t_h + i0) = __nv_bfloat162(h0, h1);
                *(__nv_bfloat162*)(t_l + i0) = __nv_bfloat162(l0, l1);
                *(__nv_bfloat162*)(t_h + i1) = __nv_bfloat162(h2, h3);
                *(__nv_bfloat162*)(t_l + i1) = __nv_bfloat162(l2, l3);
            } else {
                #pragma unroll
                for (int e = 0; e < 4; e++) {
                    const int rr = r0 + (e >> 1) * 8;        // enc row
                    const int cn = c + (e & 1);              // unit
                    const size_t idx = (size_t)(rr >> 11) * ((size_t)UNITS * SENC)
                                     + (size_t)cn * SENC + (rr & 2047);
                    vt[idx] = __float2half(a[e]);
                }
            }
        }
    }
}

// ---------------------------------------------------------------------------
// Scores: S[b] = T[b] @ enc[b]^T, BM=128, BN=128, K=512, TERMS=3, fp32 out.
// grid = (16, 8, 8)
// ---------------------------------------------------------------------------
__global__ void __launch_bounds__(256, 2)
scores_kernel(const bf16* t_h, const bf16* t_l,
              const bf16* enc_h, const bf16* enc_l, float* __restrict__ S)
{
    extern __shared__ __align__(128) char smem[];
    const int z = blockIdx.z;
    const int m0 = blockIdx.y * 128;
    const int n0 = blockIdx.x * 128;

    float acc[4][4][4];
    #pragma unroll
    for (int i = 0; i < 4; i++)
        #pragma unroll
        for (int j = 0; j < 4; j++)
            #pragma unroll
            for (int e = 0; e < 4; e++) acc[i][j][e] = 0.f;

    gemm_mainloop<3, false, 2>(
        (const uint16_t*)t_h, (const uint16_t*)t_l,
        (const uint16_t*)enc_h, (const uint16_t*)enc_l,
        ((long long)z * SDEC + m0) * DIN,
        ((long long)z * SENC + n0) * DIN, DIN, acc, smem);

    const int wid = threadIdx.x >> 5, lane = threadIdx.x & 31;
    const int rr0 = m0 + (wid >> 2) * 64 + (lane >> 2);
    const int cc0 = n0 + (wid & 3) * 32 + (lane & 3) * 2;
    float* Sb = S + (long long)z * SDEC * SENC;

    #pragma unroll
    for (int i = 0; i < 4; i++) {
        #pragma unroll
        for (int j = 0; j < 4; j++) {
            const float* a = acc[i][j];
            const int r0 = rr0 + i * 16;
            const int c  = cc0 + j * 8;
            *(float2*)(Sb + (long long)r0 * SENC + c)       = make_float2(a[0], a[1]);
            *(float2*)(Sb + (long long)(r0 + 8) * SENC + c) = make_float2(a[2], a[3]);
        }
    }
}

// ---------------------------------------------------------------------------
// PV: out[b] = P[b] @ V[b]. BM=128, BN=128, K=2048, fp16, NSTG=4. grid (4, 8, 8)
// ---------------------------------------------------------------------------
__global__ void __launch_bounds__(256, 2)
pv_kernel(const __half* P, const __half* VT, float* __restrict__ O)
{
    extern __shared__ __align__(128) char smem[];
    const int z = blockIdx.z;
    const int m0 = blockIdx.y * 128;
    const int n0 = blockIdx.x * 128;

    float acc[4][4][4];
    #pragma unroll
    for (int i = 0; i < 4; i++)
        #pragma unroll
        for (int j = 0; j < 4; j++)
            #pragma unroll
            for (int e = 0; e < 4; e++) acc[i][j][e] = 0.f;

    gemm_mainloop<1, true, 4>(
        (const uint16_t*)P, nullptr, (const uint16_t*)VT, nullptr,
        ((long long)z * SDEC + m0) * SENC,
        ((long long)z * UNITS + n0) * SENC, SENC, acc, smem);

    const int wid = threadIdx.x >> 5, lane = threadIdx.x & 31;
    const int rr0 = m0 + (wid >> 2) * 64 + (lane >> 2);
    const int cc0 = n0 + (wid & 3) * 32 + (lane & 3) * 2;
    float* Ob = O + (long long)z * SDEC * UNITS;

    #pragma unroll
    for (int i = 0; i < 4; i++) {
        #pragma unroll
        for (int j = 0; j < 4; j++) {
            const float* a = acc[i][j];
            const int r0 = rr0 + i * 16;
            const int c  = cc0 + j * 8;
            *(float2*)(Ob + (long long)r0 * UNITS + c)       = make_float2(a[0], a[1]);
            *(float2*)(Ob + (long long)(r0 + 8) * UNITS + c) = make_float2(a[2], a[3]);
        }
    }
}

// ---------------------------------------------------------------------------
// MT = Wk * Wq^T (fp32 SIMT, exact), split-bf16 output. 32x32 tiles, grid 16x16.
// ---------------------------------------------------------------------------
__global__ void __launch_bounds__(256)
mgemm_kernel(const float* __restrict__ Wk, const float* __restrict__ Wq,
             bf16* __restrict__ mh, bf16* __restrict__ ml)
{
    __shared__ float As[16][36];
    __shared__ float Bs[16][36];
    const int e0 = blockIdx.y * 32, d0 = blockIdx.x * 32;
    const int tid = threadIdx.x;
    const int ty = tid >> 4, tx = tid & 15;

    float c00 = 0.f, c01 = 0.f, c10 = 0.f, c11 = 0.f;

    for (int u0 = 0; u0 < 512; u0 += 16) {
        {
            const int t = tid & 127;
            const int row = t >> 2, col = (t & 3) * 4;
            if (tid < 128) {
                float4 a = *(const float4*)(Wk + (size_t)(e0 + row) * 512 + u0 + col);
                As[col+0][row] = a.x; As[col+1][row] = a.y;
                As[col+2][row] = a.z; As[col+3][row] = a.w;
            } else {
                float4 b = *(const float4*)(Wq + (size_t)(d0 + row) * 512 + u0 + col);
                Bs[col+0][row] = b.x; Bs[col+1][row] = b.y;
                Bs[col+2][row] = b.z; Bs[col+3][row] = b.w;
            }
        }
        __syncthreads();
        #pragma unroll
        for (int k = 0; k < 16; k++) {
            float a0 = As[k][ty*2], a1 = As[k][ty*2+1];
            float b0 = Bs[k][tx*2], b1 = Bs[k][tx*2+1];
            c00 += a0*b0; c01 += a0*b1; c10 += a1*b0; c11 += a1*b1;
        }
        __syncthreads();
    }
    bf16 h, l;
    size_t i0 = (size_t)(e0 + ty*2) * 512 + d0 + tx*2;
    size_t i1 = i0 + 512;
    split2(c00, h, l); mh[i0]   = h; ml[i0]   = l;
    split2(c01, h, l); mh[i0+1] = h; ml[i0+1] = l;
    split2(c10, h, l); mh[i1]   = h; ml[i1]   = l;
    split2(c11, h, l); mh[i1+1] = h; ml[i1+1] = l;
}

// ---------------------------------------------------------------------------
// One merged split kernel: dec -> hi/lo, enc -> hi/lo, Wv -> W^T hi/lo
// ---------------------------------------------------------------------------
__global__ void __launch_bounds__(256)
split_all_kernel(const float4* __restrict__ dec, const float4* __restrict__ enc,
                 const float* __restrict__ Wv,
                 __nv_bfloat162* __restrict__ dh, __nv_bfloat162* __restrict__ dl,
                 __nv_bfloat162* __restrict__ eh, __nv_bfloat162* __restrict__ el,
                 bf16* __restrict__ vh, bf16* __restrict__ vl)
{
    const int b = blockIdx.x;
    if (b < 12288) {
        const float4* X; __nv_bfloat162 *hi, *lo; int i;
        if (b < 4096) { X = dec; hi = dh; lo = dl; i = b * 256 + threadIdx.x; }
        else          { X = enc; hi = eh; lo = el; i = (b - 4096) * 256 + threadIdx.x; }
        float4 v = X[i];
        bf16 h0,l0,h1,l1,h2,l2,h3,l3;
        split2(v.x,h0,l0); split2(v.y,h1,l1); split2(v.z,h2,l2); split2(v.w,h3,l3);
        hi[2*i]   = __nv_bfloat162(h0,h1);
        hi[2*i+1] = __nv_bfloat162(h2,h3);
        lo[2*i]   = __nv_bfloat162(l0,l1);
        lo[2*i+1] = __nv_bfloat162(l2,l3);
    } else {
        int idx = (b - 12288) * 256 + threadIdx.x;   // [0, 262144)
        int k = idx >> 9, n = idx & 511;
        bf16 h, l; split2(Wv[idx], h, l);
        vh[n * 512 + k] = h;
        vl[n * 512 + k] = l;
    }
}

// ---------------------------------------------------------------------------
// Row softmax over 2048 fp32 scores -> fp16 probabilities
// ---------------------------------------------------------------------------
__inline__ __device__ float warpMax(float v) {
    #pragma unroll
    for (int o = 16; o; o >>= 1) v = fmaxf(v, __shfl_xor_sync(0xffffffffu, v, o));
    return v;
}
__inline__ __device__ float warpSum(float v) {
    #pragma unroll
    for (int o = 16; o; o >>= 1) v += __shfl_xor_sync(0xffffffffu, v, o);
    return v;
}

__global__ void __launch_bounds__(256)
softmax_h(const float* __restrict__ S, __half* __restrict__ P)
{
    const long long row = blockIdx.x;
    const float4* p = (const float4*)(S + row * (long long)SENC);
    const int tid = threadIdx.x, lane = tid & 31, wid = tid >> 5;

    float4 v0 = p[tid];
    float4 v1 = p[tid + 256];

    float m = fmaxf(fmaxf(fmaxf(v0.x, v0.y), fmaxf(v0.z, v0.w)),
                    fmaxf(fmaxf(v1.x, v1.y), fmaxf(v1.z, v1.w)));
    __shared__ float smax[8], ssum[8];
    m = warpMax(m);
    if (lane == 0) smax[wid] = m;
    __syncthreads();
    float bm = smax[0];
    #pragma unroll
    for (int i = 1; i < 8; i++) bm = fmaxf(bm, smax[i]);

    v0.x = __expf(v0.x - bm); v0.y = __expf(v0.y - bm);
    v0.z = __expf(v0.z - bm); v0.w = __expf(v0.w - bm);
    v1.x = __expf(v1.x - bm); v1.y = __expf(v1.y - bm);
    v1.z = __expf(v1.z - bm); v1.w = __expf(v1.w - bm);

    float s = (v0.x + v0.y + v0.z + v0.w) + (v1.x + v1.y + v1.z + v1.w);
    s = warpSum(s);
    if (lane == 0) ssum[wid] = s;
    __syncthreads();
    float bs = 0.f;
    #pragma unroll
    for (int i = 0; i < 8; i++) bs += ssum[i];
    const float inv = 1.0f / bs;

    __half2* ph = (__half2*)(P + row * (long long)SENC);
    ph[2*tid]         = __floats2half2_rn(v0.x * inv, v0.y * inv);
    ph[2*tid+1]       = __floats2half2_rn(v0.z * inv, v0.w * inv);
    ph[512 + 2*tid]   = __floats2half2_rn(v1.x * inv, v1.y * inv);
    ph[512 + 2*tid+1] = __floats2half2_rn(v1.z * inv, v1.w * inv);
}

// ---------------------------------------------------------------------------
extern "C" void kernel_launch(void* const* d_in, const int* in_sizes, int n_in,
                              void* d_out, int out_size)
{
    const float* enc = (const float*)d_in[0];
    const float* dec = (const float*)d_in[1];
    const float* Wq  = (const float*)d_in[2];
    const float* Wk  = (const float*)d_in[3];
    const float* Wv  = (const float*)d_in[4];
    float* out = (float*)d_out;

    bf16 *dec_h,*dec_l,*enc_h,*enc_l,*wvT_h,*wvT_l,*mt_h,*mt_l,*t_h,*t_l;
    __half *vt16, *p16;
    float *s;
    cudaGetSymbolAddress((void**)&dec_h, g_dec_h);
    cudaGetSymbolAddress((void**)&dec_l, g_dec_l);
    cudaGetSymbolAddress((void**)&enc_h, g_enc_h);
    cudaGetSymbolAddress((void**)&enc_l, g_enc_l);
    cudaGetSymbolAddress((void**)&wvT_h, g_wvT_h);
    cudaGetSymbolAddress((void**)&wvT_l, g_wvT_l);
    cudaGetSymbolAddress((void**)&mt_h, g_mt_h);
    cudaGetSymbolAddress((void**)&mt_l, g_mt_l);
    cudaGetSymbolAddress((void**)&t_h, g_t_h);
    cudaGetSymbolAddress((void**)&t_l, g_t_l);
    cudaGetSymbolAddress((void**)&vt16, g_vt16);
    cudaGetSymbolAddress((void**)&p16, g_p16);
    cudaGetSymbolAddress((void**)&s, g_s);

    cudaFuncSetAttribute(projvt_kernel, cudaFuncAttributeMaxDynamicSharedMemorySize, SMEM_G3);
    cudaFuncSetAttribute(scores_kernel, cudaFuncAttributeMaxDynamicSharedMemorySize, SMEM_G3);
    cudaFuncSetAttribute(pv_kernel,     cudaFuncAttributeMaxDynamicSharedMemorySize, SMEM_PV);

    // 1. all input splits (dec, enc, Wv^T) in one launch
    split_all_kernel<<<13312, 256>>>(
        (const float4*)dec, (const float4*)enc, Wv,
        (__nv_bfloat162*)dec_h, (__nv_bfloat162*)dec_l,
        (__nv_bfloat162*)enc_h, (__nv_bfloat162*)enc_l,
        wvT_h, wvT_l);

    // 2. MT = Wk * Wq^T (exact fp32) -> split bf16
    mgemm_kernel<<<dim3(16, 16), 256>>>(Wk, Wq, mt_h, mt_l);

    // 3. merged V^T projection + T = dec*M
    projvt_kernel<<<dim3(4, 192), 256, SMEM_G3>>>(
        dec_h, dec_l, enc_h, enc_l, wvT_h, wvT_l, mt_h, mt_l,
        t_h, t_l, vt16);

    // 4. scores S = T @ enc^T (batched)
    scores_kernel<<<dim3(16, 8, 8), 256, SMEM_G3>>>(t_h, t_l, enc_h, enc_l, s);

    // 5. softmax -> fp16 P
    softmax_h<<<NB * SDEC, 256>>>(s, p16);

    // 6. out = P @ V
    pv_kernel<<<dim3(4, 8, 8), 256, SMEM_PV>>>(p16, vt16, out);
}

// round 9
// speedup vs baseline: 4.5900x; 1.1800x over previous
#include <cuda_runtime.h>
#include <cuda_bf16.h>
#include <cuda_fp16.h>
#include <cstdint>

#define NB    8
#define SENC  2048
#define SDEC  1024
#define DIN   512
#define UNITS 512

using bf16 = __nv_bfloat16;

// ---------------------------------------------------------------------------
// Scratch (__device__ globals: allocation-free rule)
// ---------------------------------------------------------------------------
__device__ __align__(256) bf16 g_dec_h[(size_t)NB * SDEC * DIN];
__device__ __align__(256) bf16 g_dec_l[(size_t)NB * SDEC * DIN];
__device__ __align__(256) bf16 g_enc_h[(size_t)NB * SENC * DIN];
__device__ __align__(256) bf16 g_enc_l[(size_t)NB * SENC * DIN];
__device__ __align__(256) bf16 g_wvT_h[DIN * UNITS];
__device__ __align__(256) bf16 g_wvT_l[DIN * UNITS];
__device__ __align__(256) bf16 g_mt_h[DIN * DIN];      // MT[e][d] = (Wq Wk^T)^T
__device__ __align__(256) bf16 g_mt_l[DIN * DIN];
__device__ __align__(256) bf16 g_t_h[(size_t)NB * SDEC * DIN];   // T = dec*M
__device__ __align__(256) bf16 g_t_l[(size_t)NB * SDEC * DIN];
__device__ __align__(256) __half g_vt16[(size_t)NB * UNITS * SENC]; // V^T fp16
__device__ __align__(256) float g_s[(size_t)NB * SDEC * SENC];      // fp32 scores
__device__ __align__(256) __half g_p16[(size_t)NB * SDEC * SENC];   // P fp16

// ---------------------------------------------------------------------------
// helpers
// ---------------------------------------------------------------------------
__device__ __forceinline__ void split2(float x, bf16& h, bf16& l) {
    h = __float2bfloat16(x);
    l = __float2bfloat16(x - __bfloat162float(h));
}

#define CPA(dst, src) asm volatile( \
    "cp.async.cg.shared.global [%0], [%1], 16;" :: "r"(dst), "l"(src))
#define CP_COMMIT() asm volatile("cp.async.commit_group;")

template <int N>
__device__ __forceinline__ void cp_wait() {
    asm volatile("cp.async.wait_group %0;" :: "n"(N));
}

#define LDSM4(r0,r1,r2,r3,addr) asm volatile( \
    "ldmatrix.sync.aligned.m8n8.x4.shared.b16 {%0,%1,%2,%3}, [%4];" \
    : "=r"(r0),"=r"(r1),"=r"(r2),"=r"(r3) : "r"(addr))

#define MMA_BF16(ac,Af,B0,B1) asm volatile( \
    "mma.sync.aligned.m16n8k16.row.col.f32.bf16.bf16.f32 " \
    "{%0,%1,%2,%3}, {%4,%5,%6,%7}, {%8,%9}, {%0,%1,%2,%3};" \
    : "+f"(ac[0]),"+f"(ac[1]),"+f"(ac[2]),"+f"(ac[3]) \
    : "r"(Af[0]),"r"(Af[1]),"r"(Af[2]),"r"(Af[3]), "r"(B0),"r"(B1))

#define MMA_FP16(ac,Af,B0,B1) asm volatile( \
    "mma.sync.aligned.m16n8k16.row.col.f32.f16.f16.f32 " \
    "{%0,%1,%2,%3}, {%4,%5,%6,%7}, {%8,%9}, {%0,%1,%2,%3};" \
    : "+f"(ac[0]),"+f"(ac[1]),"+f"(ac[2]),"+f"(ac[3]) \
    : "r"(Af[0]),"r"(Af[1]),"r"(Af[2]),"r"(Af[3]), "r"(B0),"r"(B1))

// XOR-swizzled smem offset for a (row, 16B-chunk) of a 64B-wide tile.
__device__ __forceinline__ uint32_t swz(int row, int c) {
    return (uint32_t)(row * 64 + ((c ^ ((row >> 1) & 3)) << 4));
}

// ---------------------------------------------------------------------------
// 4-warp NT GEMM mainloop. BM=64, BN=128, BK=32; warps as 1x4 (warp tile
// 64x32). TERMS=3: bf16 hi/lo split (3 MMA terms). TERMS=1 & FP16: plain fp16.
// XOR-swizzled unpadded smem (64B rows). Single-sync software pipeline.
// acc[4][4][4] fp32 (m16 i, n8 j, frag e).
// ---------------------------------------------------------------------------
template <int TERMS, bool FP16, int NSTG>
__device__ __forceinline__ void gemm_mainloop(
    const uint16_t* __restrict__ Ah, const uint16_t* __restrict__ Al,
    const uint16_t* __restrict__ Bh, const uint16_t* __restrict__ Bl,
    long long aBase, long long bBase, int K,
    float acc[4][4][4], char* smem)
{
    constexpr int A_TB = 64 * 64;       // 4096 B
    constexpr int B_TB = 128 * 64;      // 8192 B
    constexpr int BOFF = (TERMS == 3) ? 2 * A_TB : A_TB;
    constexpr int STG  = (TERMS == 3) ? 2 * (A_TB + B_TB) : (A_TB + B_TB);

    const int tid  = threadIdx.x;
    const int wid  = tid >> 5;
    const int lane = tid & 31;
    const int wn = wid * 32;

    const uint32_t sm0 = (uint32_t)__cvta_generic_to_shared(smem);

    const int a_row = (lane & 7) + ((lane >> 3) & 1) * 8;
    const int a_kc  = ((lane >> 4) & 1);        // k-chunk (16B) within k16
    const int b_row = (lane & 7) + ((lane >> 4) & 1) * 8;
    const int b_kc  = ((lane >> 3) & 1);

    const int nk = K / 32;

    auto load_stage = [&](int s, int k0) {
        const uint32_t st = sm0 + s * STG;
        #pragma unroll
        for (int c = tid; c < 256; c += 128) {        // A: 64 rows x 4 chunks
            const int row = c >> 2, ch = c & 3;
            const uint32_t sa = st + swz(row, ch);
            const long long g = aBase + (long long)row * K + k0 + ch * 8;
            CPA(sa, Ah + g);
            if (TERMS == 3) CPA(sa + A_TB, Al + g);
        }
        #pragma unroll
        for (int c = tid; c < 512; c += 128) {        // B: 128 rows x 4 chunks
            const int row = c >> 2, ch = c & 3;
            const uint32_t sb = st + BOFF + swz(row, ch);
            const long long g = bBase + (long long)row * K + k0 + ch * 8;
            CPA(sb, Bh + g);
            if (TERMS == 3) CPA(sb + B_TB, Bl + g);
        }
    };

    #pragma unroll
    for (int s = 0; s < NSTG - 1; s++) {
        load_stage(s, s * 32);
        CP_COMMIT();
    }

    for (int kt = 0; kt < nk; kt++) {
        cp_wait<NSTG - 2>();
        __syncthreads();

        const int knext = kt + NSTG - 1;
        if (knext < nk)
            load_stage(knext % NSTG, knext * 32);     // overlaps compute
        CP_COMMIT();

        const uint32_t st  = sm0 + (kt % NSTG) * STG;
        const uint32_t stA = st, stB = st + BOFF;

        #pragma unroll
        for (int ks = 0; ks < 2; ks++) {
            const int kc = ks * 2;                    // 16B chunk base of k16
            uint32_t ah[4][4], al[4][4];
            #pragma unroll
            for (int i = 0; i < 4; i++) {
                const int row = i * 16 + a_row;
                const uint32_t off = swz(row, kc + a_kc);
                LDSM4(ah[i][0], ah[i][1], ah[i][2], ah[i][3], stA + off);
                if (TERMS == 3)
                    LDSM4(al[i][0], al[i][1], al[i][2], al[i][3], stA + A_TB + off);
            }
            #pragma unroll
            for (int j2 = 0; j2 < 2; j2++) {
                uint32_t bh[4], bl[4];
                const int row = wn + j2 * 16 + b_row;
                const uint32_t off = swz(row, kc + b_kc);
                LDSM4(bh[0], bh[1], bh[2], bh[3], stB + off);
                if (TERMS == 3)
                    LDSM4(bl[0], bl[1], bl[2], bl[3], stB + B_TB + off);
                #pragma unroll
                for (int i = 0; i < 4; i++) {
                    if (FP16) {
                        MMA_FP16(acc[i][2*j2],   ah[i], bh[0], bh[1]);
                        MMA_FP16(acc[i][2*j2+1], ah[i], bh[2], bh[3]);
                    } else {
                        MMA_BF16(acc[i][2*j2],   ah[i], bh[0], bh[1]);
                        MMA_BF16(acc[i][2*j2+1], ah[i], bh[2], bh[3]);
                        if (TERMS == 3) {
                            MMA_BF16(acc[i][2*j2],   ah[i], bl[0], bl[1]);
                            MMA_BF16(acc[i][2*j2],   al[i], bh[0], bh[1]);
                            MMA_BF16(acc[i][2*j2+1], ah[i], bl[2], bl[3]);
                            MMA_BF16(acc[i][2*j2+1], al[i], bh[2], bh[3]);
                        }
                    }
                }
            }
        }
    }
}

constexpr int SMEM_G3 = 2 * 2 * (64 * 64 + 128 * 64);   // 49152 (TERMS=3, NST=2)
constexpr int SMEM_PV = 4 * (64 * 64 + 128 * 64);       // 49152 (fp16, NST=4)

// ---------------------------------------------------------------------------
// Merged V-projection + T kernel. BM=64, BN=128, K=512, TERMS=3.
// grid (4, 384): y<256 -> V = enc*Wv (fp16 V^T epilogue)
//                else  -> T = dec*M  (split bf16 epilogue)
// ---------------------------------------------------------------------------
__global__ void __launch_bounds__(128, 4)
projvt_kernel(const bf16* dec_h, const bf16* dec_l,
              const bf16* enc_h, const bf16* enc_l,
              const bf16* wv_h, const bf16* wv_l,
              const bf16* mt_h, const bf16* mt_l,
              bf16* t_h, bf16* t_l, __half* vt)
{
    extern __shared__ __align__(128) char smem[];
    const int y = blockIdx.y;
    const int n0 = blockIdx.x * 128;

    const uint16_t *Ah, *Al, *Bh, *Bl;
    int mode, arow0;
    if (y < 256) {
        Ah = (const uint16_t*)enc_h; Al = (const uint16_t*)enc_l;
        Bh = (const uint16_t*)wv_h;  Bl = (const uint16_t*)wv_l;
        mode = 2; arow0 = y * 64;
    } else {
        Ah = (const uint16_t*)dec_h; Al = (const uint16_t*)dec_l;
        Bh = (const uint16_t*)mt_h;  Bl = (const uint16_t*)mt_l;
        mode = 1; arow0 = (y - 256) * 64;
    }

    float acc[4][4][4];
    #pragma unroll
    for (int i = 0; i < 4; i++)
        #pragma unroll
        for (int j = 0; j < 4; j++)
            #pragma unroll
            for (int e = 0; e < 4; e++) acc[i][j][e] = 0.f;

    gemm_mainloop<3, false, 2>(Ah, Al, Bh, Bl,
        (long long)arow0 * DIN, (long long)n0 * DIN, DIN, acc, smem);

    const int wid = threadIdx.x >> 5, lane = threadIdx.x & 31;
    const int rr0 = arow0 + (lane >> 2);
    const int cc0 = n0 + wid * 32 + (lane & 3) * 2;

    #pragma unroll
    for (int i = 0; i < 4; i++) {
        #pragma unroll
        for (int j = 0; j < 4; j++) {
            const float* a = acc[i][j];
            const int r0 = rr0 + i * 16;
            const int c  = cc0 + j * 8;
            if (mode == 1) {
                bf16 h0,l0,h1,l1,h2,l2,h3,l3;
                split2(a[0],h0,l0); split2(a[1],h1,l1);
                split2(a[2],h2,l2); split2(a[3],h3,l3);
                const size_t i0 = (size_t)r0 * DIN + c;
                const size_t i1 = (size_t)(r0 + 8) * DIN + c;
                *(__nv_bfloat162*)(t_h + i0) = __nv_bfloat162(h0, h1);
                *(__nv_bfloat162*)(t_l + i0) = __nv_bfloat162(l0, l1);
                *(__nv_bfloat162*)(t_h + i1) = __nv_bfloat162(h2, h3);
                *(__nv_bfloat162*)(t_l + i1) = __nv_bfloat162(l2, l3);
            } else {
                #pragma unroll
                for (int e = 0; e < 4; e++) {
                    const int rr = r0 + (e >> 1) * 8;        // enc row
                    const int cn = c + (e & 1);              // unit
                    const size_t idx = (size_t)(rr >> 11) * ((size_t)UNITS * SENC)
                                     + (size_t)cn * SENC + (rr & 2047);
                    vt[idx] = __float2half(a[e]);
                }
            }
        }
    }
}

// ---------------------------------------------------------------------------
// Scores: S[b] = T[b] @ enc[b]^T, BM=64, BN=128, K=512, TERMS=3, fp32 out.
// grid = (16, 16, 8)
// ---------------------------------------------------------------------------
__global__ void __launch_bounds__(128, 4)
scores_kernel(const bf16* t_h, const bf16* t_l,
              const bf16* enc_h, const bf16* enc_l, float* __restrict__ S)
{
    extern __shared__ __align__(128) char smem[];
    const int z = blockIdx.z;
    const int m0 = blockIdx.y * 64;
    const int n0 = blockIdx.x * 128;

    float acc[4][4][4];
    #pragma unroll
    for (int i = 0; i < 4; i++)
        #pragma unroll
        for (int j = 0; j < 4; j++)
            #pragma unroll
            for (int e = 0; e < 4; e++) acc[i][j][e] = 0.f;

    gemm_mainloop<3, false, 2>(
        (const uint16_t*)t_h, (const uint16_t*)t_l,
        (const uint16_t*)enc_h, (const uint16_t*)enc_l,
        ((long long)z * SDEC + m0) * DIN,
        ((long long)z * SENC + n0) * DIN, DIN, acc, smem);

    const int wid = threadIdx.x >> 5, lane = threadIdx.x & 31;
    const int rr0 = m0 + (lane >> 2);
    const int cc0 = n0 + wid * 32 + (lane & 3) * 2;
    float* Sb = S + (long long)z * SDEC * SENC;

    #pragma unroll
    for (int i = 0; i < 4; i++) {
        #pragma unroll
        for (int j = 0; j < 4; j++) {
            const float* a = acc[i][j];
            const int r0 = rr0 + i * 16;
            const int c  = cc0 + j * 8;
            *(float2*)(Sb + (long long)r0 * SENC + c)       = make_float2(a[0], a[1]);
            *(float2*)(Sb + (long long)(r0 + 8) * SENC + c) = make_float2(a[2], a[3]);
        }
    }
}

// ---------------------------------------------------------------------------
// PV: out[b] = P[b] @ V[b]. BM=64, BN=128, K=2048, fp16, NSTG=4. grid (4,16,8)
// ---------------------------------------------------------------------------
__global__ void __launch_bounds__(128, 4)
pv_kernel(const __half* P, const __half* VT, float* __restrict__ O)
{
    extern __shared__ __align__(128) char smem[];
    const int z = blockIdx.z;
    const int m0 = blockIdx.y * 64;
    const int n0 = blockIdx.x * 128;

    float acc[4][4][4];
    #pragma unroll
    for (int i = 0; i < 4; i++)
        #pragma unroll
        for (int j = 0; j < 4; j++)
            #pragma unroll
            for (int e = 0; e < 4; e++) acc[i][j][e] = 0.f;

    gemm_mainloop<1, true, 4>(
        (const uint16_t*)P, nullptr, (const uint16_t*)VT, nullptr,
        ((long long)z * SDEC + m0) * SENC,
        ((long long)z * UNITS + n0) * SENC, SENC, acc, smem);

    const int wid = threadIdx.x >> 5, lane = threadIdx.x & 31;
    const int rr0 = m0 + (lane >> 2);
    const int cc0 = n0 + wid * 32 + (lane & 3) * 2;
    float* Ob = O + (long long)z * SDEC * UNITS;

    #pragma unroll
    for (int i = 0; i < 4; i++) {
        #pragma unroll
        for (int j = 0; j < 4; j++) {
            const float* a = acc[i][j];
            const int r0 = rr0 + i * 16;
            const int c  = cc0 + j * 8;
            *(float2*)(Ob + (long long)r0 * UNITS + c)       = make_float2(a[0], a[1]);
            *(float2*)(Ob + (long long)(r0 + 8) * UNITS + c) = make_float2(a[2], a[3]);
        }
    }
}

// ---------------------------------------------------------------------------
// MT = Wk * Wq^T (fp32 SIMT, exact), split-bf16 output. 32x32 tiles, grid 16x16.
// ---------------------------------------------------------------------------
__global__ void __launch_bounds__(256)
mgemm_kernel(const float* __restrict__ Wk, const float* __restrict__ Wq,
             bf16* __restrict__ mh, bf16* __restrict__ ml)
{
    __shared__ float As[16][36];
    __shared__ float Bs[16][36];
    const int e0 = blockIdx.y * 32, d0 = blockIdx.x * 32;
    const int tid = threadIdx.x;
    const int ty = tid >> 4, tx = tid & 15;

    float c00 = 0.f, c01 = 0.f, c10 = 0.f, c11 = 0.f;

    for (int u0 = 0; u0 < 512; u0 += 16) {
        {
            const int t = tid & 127;
            const int row = t >> 2, col = (t & 3) * 4;
            if (tid < 128) {
                float4 a = *(const float4*)(Wk + (size_t)(e0 + row) * 512 + u0 + col);
                As[col+0][row] = a.x; As[col+1][row] = a.y;
                As[col+2][row] = a.z; As[col+3][row] = a.w;
            } else {
                float4 b = *(const float4*)(Wq + (size_t)(d0 + row) * 512 + u0 + col);
                Bs[col+0][row] = b.x; Bs[col+1][row] = b.y;
                Bs[col+2][row] = b.z; Bs[col+3][row] = b.w;
            }
        }
        __syncthreads();
        #pragma unroll
        for (int k = 0; k < 16; k++) {
            float a0 = As[k][ty*2], a1 = As[k][ty*2+1];
            float b0 = Bs[k][tx*2], b1 = Bs[k][tx*2+1];
            c00 += a0*b0; c01 += a0*b1; c10 += a1*b0; c11 += a1*b1;
        }
        __syncthreads();
    }
    bf16 h, l;
    size_t i0 = (size_t)(e0 + ty*2) * 512 + d0 + tx*2;
    size_t i1 = i0 + 512;
    split2(c00, h, l); mh[i0]   = h; ml[i0]   = l;
    split2(c01, h, l); mh[i0+1] = h; ml[i0+1] = l;
    split2(c10, h, l); mh[i1]   = h; ml[i1]   = l;
    split2(c11, h, l); mh[i1+1] = h; ml[i1+1] = l;
}

// ---------------------------------------------------------------------------
// One merged split kernel: dec -> hi/lo, enc -> hi/lo, Wv -> W^T hi/lo
// ---------------------------------------------------------------------------
__global__ void __launch_bounds__(256)
split_all_kernel(const float4* __restrict__ dec, const float4* __restrict__ enc,
                 const float* __restrict__ Wv,
                 __nv_bfloat162* __restrict__ dh, __nv_bfloat162* __restrict__ dl,
                 __nv_bfloat162* __restrict__ eh, __nv_bfloat162* __restrict__ el,
                 bf16* __restrict__ vh, bf16* __restrict__ vl)
{
    const int b = blockIdx.x;
    if (b < 12288) {
        const float4* X; __nv_bfloat162 *hi, *lo; int i;
        if (b < 4096) { X = dec; hi = dh; lo = dl; i = b * 256 + threadIdx.x; }
        else          { X = enc; hi = eh; lo = el; i = (b - 4096) * 256 + threadIdx.x; }
        float4 v = X[i];
        bf16 h0,l0,h1,l1,h2,l2,h3,l3;
        split2(v.x,h0,l0); split2(v.y,h1,l1); split2(v.z,h2,l2); split2(v.w,h3,l3);
        hi[2*i]   = __nv_bfloat162(h0,h1);
        hi[2*i+1] = __nv_bfloat162(h2,h3);
        lo[2*i]   = __nv_bfloat162(l0,l1);
        lo[2*i+1] = __nv_bfloat162(l2,l3);
    } else {
        int idx = (b - 12288) * 256 + threadIdx.x;   // [0, 262144)
        int k = idx >> 9, n = idx & 511;
        bf16 h, l; split2(Wv[idx], h, l);
        vh[n * 512 + k] = h;
        vl[n * 512 + k] = l;
    }
}

// ---------------------------------------------------------------------------
// Row softmax over 2048 fp32 scores -> fp16 probabilities
// ---------------------------------------------------------------------------
__inline__ __device__ float warpMax(float v) {
    #pragma unroll
    for (int o = 16; o; o >>= 1) v = fmaxf(v, __shfl_xor_sync(0xffffffffu, v, o));
    return v;
}
__inline__ __device__ float warpSum(float v) {
    #pragma unroll
    for (int o = 16; o; o >>= 1) v += __shfl_xor_sync(0xffffffffu, v, o);
    return v;
}

__global__ void __launch_bounds__(256)
softmax_h(const float* __restrict__ S, __half* __restrict__ P)
{
    const long long row = blockIdx.x;
    const float4* p = (const float4*)(S + row * (long long)SENC);
    const int tid = threadIdx.x, lane = tid & 31, wid = tid >> 5;

    float4 v0 = p[tid];
    float4 v1 = p[tid + 256];

    float m = fmaxf(fmaxf(fmaxf(v0.x, v0.y), fmaxf(v0.z, v0.w)),
                    fmaxf(fmaxf(v1.x, v1.y), fmaxf(v1.z, v1.w)));
    __shared__ float smax[8], ssum[8];
    m = warpMax(m);
    if (lane == 0) smax[wid] = m;
    __syncthreads();
    float bm = smax[0];
    #pragma unroll
    for (int i = 1; i < 8; i++) bm = fmaxf(bm, smax[i]);

    v0.x = __expf(v0.x - bm); v0.y = __expf(v0.y - bm);
    v0.z = __expf(v0.z - bm); v0.w = __expf(v0.w - bm);
    v1.x = __expf(v1.x - bm); v1.y = __expf(v1.y - bm);
    v1.z = __expf(v1.z - bm); v1.w = __expf(v1.w - bm);

    float s = (v0.x + v0.y + v0.z + v0.w) + (v1.x + v1.y + v1.z + v1.w);
    s = warpSum(s);
    if (lane == 0) ssum[wid] = s;
    __syncthreads();
    float bs = 0.f;
    #pragma unroll
    for (int i = 0; i < 8; i++) bs += ssum[i];
    const float inv = 1.0f / bs;

    __half2* ph = (__half2*)(P + row * (long long)SENC);
    ph[2*tid]         = __floats2half2_rn(v0.x * inv, v0.y * inv);
    ph[2*tid+1]       = __floats2half2_rn(v0.z * inv, v0.w * inv);
    ph[512 + 2*tid]   = __floats2half2_rn(v1.x * inv, v1.y * inv);
    ph[512 + 2*tid+1] = __floats2half2_rn(v1.z * inv, v1.w * inv);
}

// ---------------------------------------------------------------------------
extern "C" void kernel_launch(void* const* d_in, const int* in_sizes, int n_in,
                              void* d_out, int out_size)
{
    const float* enc = (const float*)d_in[0];
    const float* dec = (const float*)d_in[1];
    const float* Wq  = (const float*)d_in[2];
    const float* Wk  = (const float*)d_in[3];
    const float* Wv  = (const float*)d_in[4];
    float* out = (float*)d_out;

    bf16 *dec_h,*dec_l,*enc_h,*enc_l,*wvT_h,*wvT_l,*mt_h,*mt_l,*t_h,*t_l;
    __half *vt16, *p16;
    float *s;
    cudaGetSymbolAddress((void**)&dec_h, g_dec_h);
    cudaGetSymbolAddress((void**)&dec_l, g_dec_l);
    cudaGetSymbolAddress((void**)&enc_h, g_enc_h);
    cudaGetSymbolAddress((void**)&enc_l, g_enc_l);
    cudaGetSymbolAddress((void**)&wvT_h, g_wvT_h);
    cudaGetSymbolAddress((void**)&wvT_l, g_wvT_l);
    cudaGetSymbolAddress((void**)&mt_h, g_mt_h);
    cudaGetSymbolAddress((void**)&mt_l, g_mt_l);
    cudaGetSymbolAddress((void**)&t_h, g_t_h);
    cudaGetSymbolAddress((void**)&t_l, g_t_l);
    cudaGetSymbolAddress((void**)&vt16, g_vt16);
    cudaGetSymbolAddress((void**)&p16, g_p16);
    cudaGetSymbolAddress((void**)&s, g_s);

    cudaFuncSetAttribute(projvt_kernel, cudaFuncAttributeMaxDynamicSharedMemorySize, SMEM_G3);
    cudaFuncSetAttribute(scores_kernel, cudaFuncAttributeMaxDynamicSharedMemorySize, SMEM_G3);
    cudaFuncSetAttribute(pv_kernel,     cudaFuncAttributeMaxDynamicSharedMemorySize, SMEM_PV);

    // 1. all input splits (dec, enc, Wv^T) in one launch
    split_all_kernel<<<13312, 256>>>(
        (const float4*)dec, (const float4*)enc, Wv,
        (__nv_bfloat162*)dec_h, (__nv_bfloat162*)dec_l,
        (__nv_bfloat162*)enc_h, (__nv_bfloat162*)enc_l,
        wvT_h, wvT_l);

    // 2. MT = Wk * Wq^T (exact fp32) -> split bf16
    mgemm_kernel<<<dim3(16, 16), 256>>>(Wk, Wq, mt_h, mt_l);

    // 3. merged V^T projection + T = dec*M
    projvt_kernel<<<dim3(4, 384), 128, SMEM_G3>>>(
        dec_h, dec_l, enc_h, enc_l, wvT_h, wvT_l, mt_h, mt_l,
        t_h, t_l, vt16);

    // 4. scores S = T @ enc^T (batched)
    scores_kernel<<<dim3(16, 16, 8), 128, SMEM_G3>>>(t_h, t_l, enc_h, enc_l, s);

    // 5. softmax -> fp16 P
    softmax_h<<<NB * SDEC, 256>>>(s, p16);

    // 6. out = P @ V
    pv_kernel<<<dim3(4, 16, 8), 128, SMEM_PV>>>(p16, vt16, out);
}